// round 2
// baseline (speedup 1.0000x reference)
#include <cuda_runtime.h>
#include <cuda_bf16.h>
#include <math.h>

// Problem constants
#define BATCH   2
#define NSEQ    32768          // H*W*D = 32*32*32
#define NC      256            // channels
#define NHEADS  8
#define DH      32             // head dim
#define NROWS   (BATCH*NSEQ)   // 65536
#define FFDIM   1024
#define LN_EPS  1e-3f
#define NSPLIT  32             // split-K chunks for context accumulation

// ---------------- scratch (static __device__, no allocation) ----------------
__device__ float g_Qp[(size_t)NROWS * NC];
__device__ float g_Kp[(size_t)NROWS * NC];
__device__ float g_Vp[(size_t)NROWS * NC];
__device__ float g_x [(size_t)NROWS * NC];
__device__ float g_hidden[(size_t)NROWS * FFDIM];
__device__ float g_ffout [(size_t)NROWS * NC];
__device__ float g_partmax[(BATCH * (NSEQ/256)) * NC];   // 256 chunks x 256 cols
__device__ float g_colmax[BATCH * NC];
__device__ float g_Spart[(size_t)BATCH * NHEADS * NSPLIT * DH * DH];
__device__ float g_Zpart[(size_t)BATCH * NHEADS * NSPLIT * DH];
__device__ float g_ctx[BATCH * NHEADS * DH * DH];        // (b,h,d,e)

// ---------------- generic 128x128x8 SGEMM, bias + optional exact GELU -------
#define BM 128
#define BN 128
#define BK 8
#define TM 8
#define TN 8

__device__ __forceinline__ float gelu_exact(float v) {
    return 0.5f * v * (1.0f + erff(v * 0.70710678118654752440f));
}

template<int EPI>  // 0 = bias only, 1 = bias + gelu
__global__ __launch_bounds__(256, 2)
void sgemm_kernel(const float* __restrict__ A, const float* __restrict__ B,
                  const float* __restrict__ bias, float* __restrict__ C,
                  int M, int N, int K) {
    __shared__ float As[BK][BM];
    __shared__ float Bs[BK][BN];
    const int bx = blockIdx.x;   // N tile
    const int by = blockIdx.y;   // M tile
    const int t  = threadIdx.x;
    const int tx = t & 15;
    const int ty = t >> 4;

    const float* Ab = A + (size_t)by * BM * K;
    const float* Bb = B + (size_t)bx * BN;

    float acc[TM][TN];
    #pragma unroll
    for (int i = 0; i < TM; i++)
        #pragma unroll
        for (int j = 0; j < TN; j++) acc[i][j] = 0.0f;

    const int a_row = t >> 1;          // 0..127
    const int a_col = (t & 1) * 4;     // 0 or 4
    const int b_row = t >> 5;          // 0..7
    const int b_col = (t & 31) * 4;    // 0..124

    for (int k0 = 0; k0 < K; k0 += BK) {
        float4 av = *(const float4*)(Ab + (size_t)a_row * K + k0 + a_col);
        As[a_col + 0][a_row] = av.x;
        As[a_col + 1][a_row] = av.y;
        As[a_col + 2][a_row] = av.z;
        As[a_col + 3][a_row] = av.w;
        float4 bv = *(const float4*)(Bb + (size_t)(k0 + b_row) * N + b_col);
        *(float4*)&Bs[b_row][b_col] = bv;
        __syncthreads();

        #pragma unroll
        for (int kk = 0; kk < BK; kk++) {
            float a[TM], b[TN];
            #pragma unroll
            for (int i = 0; i < TM; i++) a[i] = As[kk][ty * TM + i];
            #pragma unroll
            for (int j = 0; j < TN; j++) b[j] = Bs[kk][tx * TN + j];
            #pragma unroll
            for (int i = 0; i < TM; i++)
                #pragma unroll
                for (int j = 0; j < TN; j++)
                    acc[i][j] = fmaf(a[i], b[j], acc[i][j]);
        }
        __syncthreads();
    }

    // epilogue: bias (+gelu), vectorized stores
    #pragma unroll
    for (int i = 0; i < TM; i++) {
        const size_t row = (size_t)by * BM + ty * TM + i;
        #pragma unroll
        for (int j = 0; j < TN; j += 4) {
            const int col = bx * BN + tx * TN + j;
            float4 v;
            v.x = acc[i][j + 0] + bias[col + 0];
            v.y = acc[i][j + 1] + bias[col + 1];
            v.z = acc[i][j + 2] + bias[col + 2];
            v.w = acc[i][j + 3] + bias[col + 3];
            if (EPI == 1) {
                v.x = gelu_exact(v.x); v.y = gelu_exact(v.y);
                v.z = gelu_exact(v.z); v.w = gelu_exact(v.w);
            }
            *(float4*)(C + row * N + col) = v;
        }
    }
}

// ---------------- K column-max over N (two stages, coalesced) ----------------
__global__ void colmax_part_kernel() {
    // each block: 256 consecutive rows of one batch, all 256 columns
    const int chunk = blockIdx.x;            // 0 .. B*128-1
    const int b = chunk / (NSEQ / 256);
    const int r0 = (chunk % (NSEQ / 256)) * 256;
    const int c = threadIdx.x;
    const float* base = g_Kp + ((size_t)b * NSEQ + r0) * NC;
    float m = -INFINITY;
    for (int r = 0; r < 256; r++) m = fmaxf(m, base[(size_t)r * NC + c]);
    g_partmax[(size_t)chunk * NC + c] = m;
}

__global__ void colmax_red_kernel() {
    const int b = blockIdx.x;
    const int c = threadIdx.x;
    float m = -INFINITY;
    for (int ch = 0; ch < NSEQ / 256; ch++)
        m = fmaxf(m, g_partmax[((size_t)(b * (NSEQ / 256) + ch)) * NC + c]);
    g_colmax[b * NC + c] = m;
}

// ---------------- context partials: S[d][e] = sum_n exp(K-max)*V ------------
__global__ __launch_bounds__(256)
void ctx_part_kernel() {
    const int s  = blockIdx.x;   // split index 0..NSPLIT-1
    const int bh = blockIdx.y;   // 0..15
    const int b = bh / NHEADS;
    const int h = bh % NHEADS;
    const int t = threadIdx.x;
    const int chunk = NSEQ / NSPLIT;   // 1024

    __shared__ float ek[8][DH];
    __shared__ float vv[8][DH];

    const int e  = t & 31;
    const int d0 = (t >> 5) * 4;

    float acc0 = 0.f, acc1 = 0.f, acc2 = 0.f, acc3 = 0.f;
    float zacc = 0.f;

    const float km0 = g_colmax[b * NC + h * DH + (t & 63) % DH]; // not used directly; keep loads simple below
    (void)km0;

    for (int g = 0; g < chunk / 8; g++) {
        // cooperative load of 8 rows x (K32 + V32)
        #pragma unroll
        for (int i = 0; i < 2; i++) {
            int idx = t + i * 256;        // 0..511
            int row = idx >> 6;           // 0..7
            int col = idx & 63;           // 0..63
            int n = s * chunk + g * 8 + row;
            size_t base = ((size_t)b * NSEQ + n) * NC + h * DH;
            if (col < DH) {
                float kv = g_Kp[base + col];
                ek[row][col] = expf(kv - g_colmax[b * NC + h * DH + col]);
            } else {
                vv[row][col - DH] = g_Vp[base + (col - DH)];
            }
        }
        __syncthreads();
        #pragma unroll
        for (int row = 0; row < 8; row++) {
            float v = vv[row][e];
            acc0 = fmaf(ek[row][d0 + 0], v, acc0);
            acc1 = fmaf(ek[row][d0 + 1], v, acc1);
            acc2 = fmaf(ek[row][d0 + 2], v, acc2);
            acc3 = fmaf(ek[row][d0 + 3], v, acc3);
        }
        if (t < DH) {
            #pragma unroll
            for (int row = 0; row < 8; row++) zacc += ek[row][t];
        }
        __syncthreads();
    }

    const size_t sp = ((size_t)bh * NSPLIT + s) * (DH * DH);
    g_Spart[sp + (d0 + 0) * DH + e] = acc0;
    g_Spart[sp + (d0 + 1) * DH + e] = acc1;
    g_Spart[sp + (d0 + 2) * DH + e] = acc2;
    g_Spart[sp + (d0 + 3) * DH + e] = acc3;
    if (t < DH) g_Zpart[((size_t)bh * NSPLIT + s) * DH + t] = zacc;
}

__global__ void ctx_reduce_kernel() {
    const int bh = blockIdx.x;   // 0..15
    const int t = threadIdx.x;   // 0..1023 => (d,e)
    const int d = t >> 5;
    __shared__ float zs[DH];
    float ssum = 0.f;
    for (int p = 0; p < NSPLIT; p++)
        ssum += g_Spart[((size_t)bh * NSPLIT + p) * (DH * DH) + t];
    if (t < DH) {
        float z = 0.f;
        for (int p = 0; p < NSPLIT; p++)
            z += g_Zpart[((size_t)bh * NSPLIT + p) * DH + t];
        zs[t] = z;
    }
    __syncthreads();
    g_ctx[(size_t)bh * (DH * DH) + t] = ssum / zs[d];
}

// ------------- fused: softmax(Q heads) -> attn -> +residual -> LN1 ----------
#define ROWS_PER_BLK 16
__global__ __launch_bounds__(256)
void attn_ln1_kernel(const float* __restrict__ qin,
                     const float* __restrict__ gamma,
                     const float* __restrict__ beta) {
    __shared__ float ctxs[NHEADS * DH * DH];  // 32 KB
    __shared__ float r1[8], r2[8];
    const int t = threadIdx.x;
    const int row0 = blockIdx.x * ROWS_PER_BLK;
    const int b = row0 / NSEQ;
    for (int i = t; i < NHEADS * DH * DH; i += 256)
        ctxs[i] = g_ctx[(size_t)b * NHEADS * DH * DH + i];
    __syncthreads();

    const int h = t >> 5;
    const int lane = t & 31;
    const float gc = gamma[t];
    const float bc = beta[t];

    for (int r = 0; r < ROWS_PER_BLK; r++) {
        const size_t off = (size_t)(row0 + r) * NC;
        float qv = g_Qp[off + t];
        // per-head softmax (warp == head)
        float m = qv;
        #pragma unroll
        for (int sft = 16; sft > 0; sft >>= 1)
            m = fmaxf(m, __shfl_xor_sync(0xffffffffu, m, sft));
        float ev = expf(qv - m);
        float ssum = ev;
        #pragma unroll
        for (int sft = 16; sft > 0; sft >>= 1)
            ssum += __shfl_xor_sync(0xffffffffu, ssum, sft);
        float qn = ev / ssum;

        float acc = 0.f;
        #pragma unroll
        for (int d = 0; d < DH; d++) {
            float qd = __shfl_sync(0xffffffffu, qn, d);
            acc = fmaf(qd, ctxs[h * (DH * DH) + d * DH + lane], acc);
        }
        float y = qin[off + t] + acc;

        // block LN over 256
        float s1 = y, s2 = y * y;
        #pragma unroll
        for (int sft = 16; sft > 0; sft >>= 1) {
            s1 += __shfl_xor_sync(0xffffffffu, s1, sft);
            s2 += __shfl_xor_sync(0xffffffffu, s2, sft);
        }
        if (lane == 0) { r1[h] = s1; r2[h] = s2; }
        __syncthreads();
        if (t == 0) {
            float a = 0.f, c2 = 0.f;
            #pragma unroll
            for (int i = 0; i < 8; i++) { a += r1[i]; c2 += r2[i]; }
            r1[0] = a; r2[0] = c2;
        }
        __syncthreads();
        float mean = r1[0] * (1.0f / NC);
        float var  = r2[0] * (1.0f / NC) - mean * mean;
        g_x[off + t] = (y - mean) * rsqrtf(var + LN_EPS) * gc + bc;
        __syncthreads();
    }
}

// ---------------- final: out = LN(x + ffout) --------------------------------
__global__ __launch_bounds__(256)
void ln2_kernel(const float* __restrict__ gamma, const float* __restrict__ beta,
                float* __restrict__ out) {
    __shared__ float r1[8], r2[8];
    const int t = threadIdx.x;
    const size_t off = (size_t)blockIdx.x * NC;
    const int h = t >> 5;
    const int lane = t & 31;
    float y = g_x[off + t] + g_ffout[off + t];
    float s1 = y, s2 = y * y;
    #pragma unroll
    for (int sft = 16; sft > 0; sft >>= 1) {
        s1 += __shfl_xor_sync(0xffffffffu, s1, sft);
        s2 += __shfl_xor_sync(0xffffffffu, s2, sft);
    }
    if (lane == 0) { r1[h] = s1; r2[h] = s2; }
    __syncthreads();
    if (t == 0) {
        float a = 0.f, c2 = 0.f;
        #pragma unroll
        for (int i = 0; i < 8; i++) { a += r1[i]; c2 += r2[i]; }
        r1[0] = a; r2[0] = c2;
    }
    __syncthreads();
    float mean = r1[0] * (1.0f / NC);
    float var  = r2[0] * (1.0f / NC) - mean * mean;
    out[off + t] = (y - mean) * rsqrtf(var + LN_EPS) * gamma[t] + beta[t];
}

// ---------------- launch ----------------------------------------------------
extern "C" void kernel_launch(void* const* d_in, const int* in_sizes, int n_in,
                              void* d_out, int out_size) {
    const float* q     = (const float*)d_in[0];
    const float* kv    = (const float*)d_in[1];
    const float* wq_w  = (const float*)d_in[2];
    const float* wq_b  = (const float*)d_in[3];
    const float* wk_w  = (const float*)d_in[4];
    const float* wk_b  = (const float*)d_in[5];
    const float* wv_w  = (const float*)d_in[6];
    const float* wv_b  = (const float*)d_in[7];
    const float* ln1_g = (const float*)d_in[8];
    const float* ln1_b = (const float*)d_in[9];
    const float* ff1_w = (const float*)d_in[10];
    const float* ff1_b = (const float*)d_in[11];
    const float* ff2_w = (const float*)d_in[12];
    const float* ff2_b = (const float*)d_in[13];
    const float* ln2_g = (const float*)d_in[14];
    const float* ln2_b = (const float*)d_in[15];
    float* out = (float*)d_out;

    void *pQ, *pK, *pV, *pX, *pH, *pF;
    cudaGetSymbolAddress(&pQ, g_Qp);
    cudaGetSymbolAddress(&pK, g_Kp);
    cudaGetSymbolAddress(&pV, g_Vp);
    cudaGetSymbolAddress(&pX, g_x);
    cudaGetSymbolAddress(&pH, g_hidden);
    cudaGetSymbolAddress(&pF, g_ffout);

    dim3 gQKV(NC / BN, NROWS / BM);        // (2, 512)
    sgemm_kernel<0><<<gQKV, 256>>>(q,  wq_w, wq_b, (float*)pQ, NROWS, NC, NC);
    sgemm_kernel<0><<<gQKV, 256>>>(kv, wk_w, wk_b, (float*)pK, NROWS, NC, NC);
    sgemm_kernel<0><<<gQKV, 256>>>(kv, wv_w, wv_b, (float*)pV, NROWS, NC, NC);

    colmax_part_kernel<<<BATCH * (NSEQ / 256), 256>>>();
    colmax_red_kernel<<<BATCH, 256>>>();

    ctx_part_kernel<<<dim3(NSPLIT, BATCH * NHEADS), 256>>>();
    ctx_reduce_kernel<<<BATCH * NHEADS, DH * DH>>>();

    attn_ln1_kernel<<<NROWS / ROWS_PER_BLK, 256>>>(q, ln1_g, ln1_b);

    dim3 gFF1(FFDIM / BN, NROWS / BM);     // (8, 512)
    sgemm_kernel<1><<<gFF1, 256>>>((const float*)pX, ff1_w, ff1_b, (float*)pH,
                                   NROWS, FFDIM, NC);
    dim3 gFF2(NC / BN, NROWS / BM);        // (2, 512)
    sgemm_kernel<0><<<gFF2, 256>>>((const float*)pH, ff2_w, ff2_b, (float*)pF,
                                   NROWS, NC, FFDIM);

    ln2_kernel<<<NROWS, 256>>>(ln2_g, ln2_b, out);
}

// round 4
// speedup vs baseline: 1.9740x; 1.9740x over previous
#include <cuda_runtime.h>
#include <cuda_bf16.h>
#include <math.h>
#include <stdint.h>

// Problem constants
#define BATCH   2
#define NSEQ    32768          // H*W*D
#define NC      256
#define NHEADS  8
#define DH      32
#define NROWS   (BATCH*NSEQ)   // 65536
#define FFDIM   1024
#define LN_EPS  1e-3f
#define NSPLIT  32

// ---------------- scratch (static __device__, no allocation) ----------------
__device__ float g_Qp[(size_t)NROWS * NC];
__device__ float g_Kp[(size_t)NROWS * NC];
__device__ float g_Vp[(size_t)NROWS * NC];
__device__ float g_x [(size_t)NROWS * NC];
__device__ float g_ffout[(size_t)NROWS * NC];
__device__ float g_partmax[(BATCH * (NSEQ/256)) * NC];
__device__ float g_colmax[BATCH * NC];
__device__ float g_Spart[(size_t)BATCH * NHEADS * NSPLIT * DH * DH];
__device__ float g_Zpart[(size_t)BATCH * NHEADS * NSPLIT * DH];
__device__ float g_ctx[BATCH * NHEADS * DH * DH];

// bf16 split operands
__device__ __nv_bfloat16 g_qhi [(size_t)NROWS * NC];
__device__ __nv_bfloat16 g_qlo [(size_t)NROWS * NC];
__device__ __nv_bfloat16 g_kvhi[(size_t)NROWS * NC];
__device__ __nv_bfloat16 g_kvlo[(size_t)NROWS * NC];
__device__ __nv_bfloat16 g_xhi [(size_t)NROWS * NC];
__device__ __nv_bfloat16 g_xlo [(size_t)NROWS * NC];
__device__ __nv_bfloat16 g_hhi [(size_t)NROWS * FFDIM];
__device__ __nv_bfloat16 g_hlo [(size_t)NROWS * FFDIM];
// transposed weights [N][K]
__device__ __nv_bfloat16 g_wqThi[NC*NC],    g_wqTlo[NC*NC];
__device__ __nv_bfloat16 g_wkThi[NC*NC],    g_wkTlo[NC*NC];
__device__ __nv_bfloat16 g_wvThi[NC*NC],    g_wvTlo[NC*NC];
__device__ __nv_bfloat16 g_f1Thi[FFDIM*NC], g_f1Tlo[FFDIM*NC];
__device__ __nv_bfloat16 g_f2Thi[NC*FFDIM], g_f2Tlo[NC*FFDIM];

// ======================= baseline-PTX helpers ===============================
__device__ __forceinline__ uint32_t smem_u32(const void* p) {
    uint32_t a;
    asm("{ .reg .u64 t; cvta.to.shared.u64 t, %1; cvt.u32.u64 %0, t; }" : "=r"(a) : "l"(p));
    return a;
}
__device__ __forceinline__ void ldsm4(uint32_t* r, uint32_t addr) {
    asm volatile("ldmatrix.sync.aligned.m8n8.x4.shared.b16 {%0,%1,%2,%3}, [%4];"
        : "=r"(r[0]), "=r"(r[1]), "=r"(r[2]), "=r"(r[3]) : "r"(addr));
}
__device__ __forceinline__ void mma16816(float* c, const uint32_t* a, const uint32_t* b) {
    asm volatile("mma.sync.aligned.m16n8k16.row.col.f32.bf16.bf16.f32 "
        "{%0,%1,%2,%3}, {%4,%5,%6,%7}, {%8,%9}, {%0,%1,%2,%3};"
        : "+f"(c[0]), "+f"(c[1]), "+f"(c[2]), "+f"(c[3])
        : "r"(a[0]), "r"(a[1]), "r"(a[2]), "r"(a[3]), "r"(b[0]), "r"(b[1]));
}
#define CP16(dst, src) \
    asm volatile("cp.async.cg.shared.global [%0], [%1], 16;" :: "r"(dst), "l"(src))
#define CP_COMMIT()  asm volatile("cp.async.commit_group;" ::: "memory")
#define CP_WAIT1()   asm volatile("cp.async.wait_group 1;" ::: "memory")
#define CP_WAIT0()   asm volatile("cp.async.wait_group 0;" ::: "memory")

__device__ __forceinline__ float gelu_exact(float v) {
    return 0.5f * v * (1.0f + erff(v * 0.70710678118654752440f));
}

// ======================= HMMA 3-term bf16 GEMM ==============================
// C[M,N] = A[M,K] @ W[K,N]; A as hi/lo bf16 [M][K], W as hi/lo bf16 [N][K].
// CTA tile 128x128, k-chunk 64, 8 warps (warp tile 64x32), double buffered.
#define KCH   64
#define BSTR  72                       // padded smem stride in bf16
#define BSTRB (BSTR*2)                 // 144 bytes
#define TILEB (128*BSTRB)              // 18432 bytes per tile-term
#define SOFF(s, t) (((s)*4 + (t)) * TILEB)
#define GEMM_SMEM (8 * TILEB)          // 147456

// issue one tile-term load: 128 rows x 64 bf16
__device__ __forceinline__ void load_tile(const __nv_bfloat16* __restrict__ src,
                                          uint32_t dstbase, int row0, int col0,
                                          int ldk, int tid) {
    const __nv_bfloat16* s = src + (size_t)(row0 + (tid >> 3)) * ldk + col0 + (tid & 7) * 8;
    uint32_t d = dstbase + (uint32_t)(tid >> 3) * BSTRB + (uint32_t)(tid & 7) * 16;
    #pragma unroll
    for (int p = 0; p < 4; p++)
        CP16(d + p * 32 * BSTRB, s + (size_t)p * 32 * ldk);
}

template<int EPI>  // 0: fp32 out + bias.  1: bias + gelu -> bf16 hi/lo out.
__global__ __launch_bounds__(256)
void tc_gemm(const __nv_bfloat16* __restrict__ Ahi, const __nv_bfloat16* __restrict__ Alo,
             const __nv_bfloat16* __restrict__ Bhi, const __nv_bfloat16* __restrict__ Blo,
             const float* __restrict__ bias,
             float* __restrict__ Cf, __nv_bfloat16* __restrict__ Chi,
             __nv_bfloat16* __restrict__ Clo, int N, int K) {
    extern __shared__ __align__(1024) char smem[];
    const uint32_t sb = smem_u32(smem);
    const int tid  = threadIdx.x;
    const int wid  = tid >> 5;
    const int lane = tid & 31;
    const int wm = wid & 1;            // 2 row groups of 64
    const int wn = wid >> 1;           // 4 col groups of 32
    const int rowA0 = blockIdx.y * 128;
    const int rowB0 = blockIdx.x * 128;
    const int nch = K / KCH;

    // per-thread ldmatrix offsets
    const int row_a  = (lane & 7) + ((lane >> 3) & 1) * 8;
    const int kcol_a = (lane >> 4) * 8;
    const uint32_t aoff = (uint32_t)(wm * 64 + row_a) * BSTRB + kcol_a * 2;
    const int row_b  = (lane & 7) + (lane >> 4) * 8;
    const int kcol_b = ((lane >> 3) & 1) * 8;
    const uint32_t boff = (uint32_t)(wn * 32 + row_b) * BSTRB + kcol_b * 2;

    float c[4][4][4];
    #pragma unroll
    for (int i = 0; i < 4; i++)
        #pragma unroll
        for (int j = 0; j < 4; j++)
            #pragma unroll
            for (int q = 0; q < 4; q++) c[i][j][q] = 0.0f;

    // prologue: stage 0
    load_tile(Ahi, sb + SOFF(0, 0), rowA0, 0, K, tid);
    load_tile(Alo, sb + SOFF(0, 1), rowA0, 0, K, tid);
    load_tile(Bhi, sb + SOFF(0, 2), rowB0, 0, K, tid);
    load_tile(Blo, sb + SOFF(0, 3), rowB0, 0, K, tid);
    CP_COMMIT();

    for (int ch = 0; ch < nch; ch++) {
        const int s = ch & 1;
        if (ch + 1 < nch) {
            const int ns = (ch + 1) & 1;
            const int col0 = (ch + 1) * KCH;
            load_tile(Ahi, sb + SOFF(ns, 0), rowA0, col0, K, tid);
            load_tile(Alo, sb + SOFF(ns, 1), rowA0, col0, K, tid);
            load_tile(Bhi, sb + SOFF(ns, 2), rowB0, col0, K, tid);
            load_tile(Blo, sb + SOFF(ns, 3), rowB0, col0, K, tid);
            CP_COMMIT();
            CP_WAIT1();
        } else {
            CP_WAIT0();
        }
        __syncthreads();

        const uint32_t aH = sb + SOFF(s, 0) + aoff;
        const uint32_t aL = sb + SOFF(s, 1) + aoff;
        const uint32_t bH = sb + SOFF(s, 2) + boff;
        const uint32_t bL = sb + SOFF(s, 3) + boff;

        #pragma unroll
        for (int ks = 0; ks < KCH / 16; ks++) {
            uint32_t ahi[4][4], alo[4][4], bhi[4][2], blo[4][2];
            #pragma unroll
            for (int mt = 0; mt < 4; mt++) {
                ldsm4(ahi[mt], aH + mt * 16 * BSTRB + ks * 32);
                ldsm4(alo[mt], aL + mt * 16 * BSTRB + ks * 32);
            }
            #pragma unroll
            for (int nt2 = 0; nt2 < 2; nt2++) {
                uint32_t r[4];
                ldsm4(r, bH + nt2 * 16 * BSTRB + ks * 32);
                bhi[nt2 * 2 + 0][0] = r[0]; bhi[nt2 * 2 + 0][1] = r[1];
                bhi[nt2 * 2 + 1][0] = r[2]; bhi[nt2 * 2 + 1][1] = r[3];
                ldsm4(r, bL + nt2 * 16 * BSTRB + ks * 32);
                blo[nt2 * 2 + 0][0] = r[0]; blo[nt2 * 2 + 0][1] = r[1];
                blo[nt2 * 2 + 1][0] = r[2]; blo[nt2 * 2 + 1][1] = r[3];
            }
            #pragma unroll
            for (int mt = 0; mt < 4; mt++)
                #pragma unroll
                for (int nt = 0; nt < 4; nt++) {
                    mma16816(c[mt][nt], ahi[mt], bhi[nt]);
                    mma16816(c[mt][nt], ahi[mt], blo[nt]);
                    mma16816(c[mt][nt], alo[mt], bhi[nt]);
                }
        }
        __syncthreads();
    }

    // ---- epilogue ----
    const int mrow = blockIdx.y * 128 + wm * 64 + (lane >> 2);
    const int ncol = blockIdx.x * 128 + wn * 32 + 2 * (lane & 3);
    #pragma unroll
    for (int mt = 0; mt < 4; mt++) {
        #pragma unroll
        for (int nt = 0; nt < 4; nt++) {
            const int col = ncol + nt * 8;
            const float b0 = bias[col], b1 = bias[col + 1];
            #pragma unroll
            for (int half = 0; half < 2; half++) {
                const int row = mrow + mt * 16 + half * 8;
                float v0 = c[mt][nt][half * 2 + 0] + b0;
                float v1 = c[mt][nt][half * 2 + 1] + b1;
                if (EPI == 0) {
                    *(float2*)(Cf + (size_t)row * N + col) = make_float2(v0, v1);
                } else {
                    v0 = gelu_exact(v0);
                    v1 = gelu_exact(v1);
                    __nv_bfloat16 h0 = __float2bfloat16_rn(v0);
                    __nv_bfloat16 h1 = __float2bfloat16_rn(v1);
                    __nv_bfloat16 l0 = __float2bfloat16_rn(v0 - __bfloat162float(h0));
                    __nv_bfloat16 l1 = __float2bfloat16_rn(v1 - __bfloat162float(h1));
                    uint32_t ph = (uint32_t)__bfloat16_as_ushort(h0) |
                                  ((uint32_t)__bfloat16_as_ushort(h1) << 16);
                    uint32_t pl = (uint32_t)__bfloat16_as_ushort(l0) |
                                  ((uint32_t)__bfloat16_as_ushort(l1) << 16);
                    *(uint32_t*)(Chi + (size_t)row * N + col) = ph;
                    *(uint32_t*)(Clo + (size_t)row * N + col) = pl;
                }
            }
        }
    }
}

// ======================= conversion kernels =================================
__global__ void conv_split_kernel(const float* __restrict__ x,
                                  __nv_bfloat16* __restrict__ hi,
                                  __nv_bfloat16* __restrict__ lo) {
    size_t i = ((size_t)blockIdx.x * blockDim.x + threadIdx.x) * 4;
    float4 v = *(const float4*)(x + i);
    __nv_bfloat16 h0 = __float2bfloat16_rn(v.x), h1 = __float2bfloat16_rn(v.y);
    __nv_bfloat16 h2 = __float2bfloat16_rn(v.z), h3 = __float2bfloat16_rn(v.w);
    __nv_bfloat16 l0 = __float2bfloat16_rn(v.x - __bfloat162float(h0));
    __nv_bfloat16 l1 = __float2bfloat16_rn(v.y - __bfloat162float(h1));
    __nv_bfloat16 l2 = __float2bfloat16_rn(v.z - __bfloat162float(h2));
    __nv_bfloat16 l3 = __float2bfloat16_rn(v.w - __bfloat162float(h3));
    uint32_t h01 = (uint32_t)__bfloat16_as_ushort(h0) | ((uint32_t)__bfloat16_as_ushort(h1) << 16);
    uint32_t h23 = (uint32_t)__bfloat16_as_ushort(h2) | ((uint32_t)__bfloat16_as_ushort(h3) << 16);
    uint32_t l01 = (uint32_t)__bfloat16_as_ushort(l0) | ((uint32_t)__bfloat16_as_ushort(l1) << 16);
    uint32_t l23 = (uint32_t)__bfloat16_as_ushort(l2) | ((uint32_t)__bfloat16_as_ushort(l3) << 16);
    *(uint2*)(hi + i) = make_uint2(h01, h23);
    *(uint2*)(lo + i) = make_uint2(l01, l23);
}

// W[K][N] fp32 -> WT[N][K] bf16 hi/lo
__global__ void convT_split_kernel(const float* __restrict__ W,
                                   __nv_bfloat16* __restrict__ thi,
                                   __nv_bfloat16* __restrict__ tlo, int K, int N) {
    __shared__ float t[32][33];
    const int n0 = blockIdx.x * 32, k0 = blockIdx.y * 32;
    const int tx = threadIdx.x, ty = threadIdx.y;
    for (int i = ty; i < 32; i += 8) t[i][tx] = W[(size_t)(k0 + i) * N + n0 + tx];
    __syncthreads();
    for (int i = ty; i < 32; i += 8) {
        float v = t[tx][i];
        size_t o = (size_t)(n0 + i) * K + k0 + tx;
        __nv_bfloat16 h = __float2bfloat16_rn(v);
        thi[o] = h;
        tlo[o] = __float2bfloat16_rn(v - __bfloat162float(h));
    }
}

// ======================= attention middle ===================================
__global__ void colmax_part_kernel() {
    const int chunk = blockIdx.x;
    const int b = chunk / (NSEQ / 256);
    const int r0 = (chunk % (NSEQ / 256)) * 256;
    const int c = threadIdx.x;
    const float* base = g_Kp + ((size_t)b * NSEQ + r0) * NC;
    float m = -INFINITY;
    for (int r = 0; r < 256; r++) m = fmaxf(m, base[(size_t)r * NC + c]);
    g_partmax[(size_t)chunk * NC + c] = m;
}
__global__ void colmax_red_kernel() {
    const int b = blockIdx.x;
    const int c = threadIdx.x;
    float m = -INFINITY;
    for (int ch = 0; ch < NSEQ / 256; ch++)
        m = fmaxf(m, g_partmax[((size_t)(b * (NSEQ / 256) + ch)) * NC + c]);
    g_colmax[b * NC + c] = m;
}
__global__ __launch_bounds__(256)
void ctx_part_kernel() {
    const int s  = blockIdx.x;
    const int bh = blockIdx.y;
    const int b = bh / NHEADS;
    const int h = bh % NHEADS;
    const int t = threadIdx.x;
    const int chunk = NSEQ / NSPLIT;
    __shared__ float ek[8][DH];
    __shared__ float vv[8][DH];
    const int e  = t & 31;
    const int d0 = (t >> 5) * 4;
    float acc0 = 0.f, acc1 = 0.f, acc2 = 0.f, acc3 = 0.f, zacc = 0.f;
    for (int g = 0; g < chunk / 8; g++) {
        #pragma unroll
        for (int i = 0; i < 2; i++) {
            int idx = t + i * 256;
            int row = idx >> 6;
            int col = idx & 63;
            int n = s * chunk + g * 8 + row;
            size_t base = ((size_t)b * NSEQ + n) * NC + h * DH;
            if (col < DH) {
                float kv = g_Kp[base + col];
                ek[row][col] = expf(kv - g_colmax[b * NC + h * DH + col]);
            } else {
                vv[row][col - DH] = g_Vp[base + (col - DH)];
            }
        }
        __syncthreads();
        #pragma unroll
        for (int row = 0; row < 8; row++) {
            float v = vv[row][e];
            acc0 = fmaf(ek[row][d0 + 0], v, acc0);
            acc1 = fmaf(ek[row][d0 + 1], v, acc1);
            acc2 = fmaf(ek[row][d0 + 2], v, acc2);
            acc3 = fmaf(ek[row][d0 + 3], v, acc3);
        }
        if (t < DH) {
            #pragma unroll
            for (int row = 0; row < 8; row++) zacc += ek[row][t];
        }
        __syncthreads();
    }
    const size_t sp = ((size_t)bh * NSPLIT + s) * (DH * DH);
    g_Spart[sp + (d0 + 0) * DH + e] = acc0;
    g_Spart[sp + (d0 + 1) * DH + e] = acc1;
    g_Spart[sp + (d0 + 2) * DH + e] = acc2;
    g_Spart[sp + (d0 + 3) * DH + e] = acc3;
    if (t < DH) g_Zpart[((size_t)bh * NSPLIT + s) * DH + t] = zacc;
}
__global__ void ctx_reduce_kernel() {
    const int bh = blockIdx.x;
    const int t = threadIdx.x;
    const int d = t >> 5;
    __shared__ float zs[DH];
    float ssum = 0.f;
    for (int p = 0; p < NSPLIT; p++)
        ssum += g_Spart[((size_t)bh * NSPLIT + p) * (DH * DH) + t];
    if (t < DH) {
        float z = 0.f;
        for (int p = 0; p < NSPLIT; p++)
            z += g_Zpart[((size_t)bh * NSPLIT + p) * DH + t];
        zs[t] = z;
    }
    __syncthreads();
    g_ctx[(size_t)bh * (DH * DH) + t] = ssum / zs[d];
}

// fused softmax(Q) -> attn -> +residual -> LN1 (emits fp32 x and bf16 hi/lo)
#define ROWS_PER_BLK 16
__global__ __launch_bounds__(256)
void attn_ln1_kernel(const float* __restrict__ qin,
                     const float* __restrict__ gamma,
                     const float* __restrict__ beta) {
    __shared__ float ctxs[NHEADS * DH * DH];
    __shared__ float r1[8], r2[8];
    const int t = threadIdx.x;
    const int row0 = blockIdx.x * ROWS_PER_BLK;
    const int b = row0 / NSEQ;
    for (int i = t; i < NHEADS * DH * DH; i += 256)
        ctxs[i] = g_ctx[(size_t)b * NHEADS * DH * DH + i];
    __syncthreads();
    const int h = t >> 5;
    const int lane = t & 31;
    const float gc = gamma[t];
    const float bc = beta[t];
    for (int r = 0; r < ROWS_PER_BLK; r++) {
        const size_t off = (size_t)(row0 + r) * NC;
        float qv = g_Qp[off + t];
        float m = qv;
        #pragma unroll
        for (int s = 16; s > 0; s >>= 1) m = fmaxf(m, __shfl_xor_sync(0xffffffffu, m, s));
        float ev = expf(qv - m);
        float ss = ev;
        #pragma unroll
        for (int s = 16; s > 0; s >>= 1) ss += __shfl_xor_sync(0xffffffffu, ss, s);
        float qn = ev / ss;
        float acc = 0.f;
        #pragma unroll
        for (int d = 0; d < DH; d++) {
            float qd = __shfl_sync(0xffffffffu, qn, d);
            acc = fmaf(qd, ctxs[h * (DH * DH) + d * DH + lane], acc);
        }
        float y = qin[off + t] + acc;
        float s1 = y, s2 = y * y;
        #pragma unroll
        for (int s = 16; s > 0; s >>= 1) {
            s1 += __shfl_xor_sync(0xffffffffu, s1, s);
            s2 += __shfl_xor_sync(0xffffffffu, s2, s);
        }
        if (lane == 0) { r1[h] = s1; r2[h] = s2; }
        __syncthreads();
        if (t == 0) {
            float a = 0.f, c2 = 0.f;
            #pragma unroll
            for (int i = 0; i < 8; i++) { a += r1[i]; c2 += r2[i]; }
            r1[0] = a; r2[0] = c2;
        }
        __syncthreads();
        float mean = r1[0] * (1.0f / NC);
        float var  = r2[0] * (1.0f / NC) - mean * mean;
        float xv = (y - mean) * rsqrtf(var + LN_EPS) * gc + bc;
        g_x[off + t] = xv;
        __nv_bfloat16 hh = __float2bfloat16_rn(xv);
        g_xhi[off + t] = hh;
        g_xlo[off + t] = __float2bfloat16_rn(xv - __bfloat162float(hh));
        __syncthreads();
    }
}

__global__ __launch_bounds__(256)
void ln2_kernel(const float* __restrict__ gamma, const float* __restrict__ beta,
                float* __restrict__ out) {
    __shared__ float r1[8], r2[8];
    const int t = threadIdx.x;
    const size_t off = (size_t)blockIdx.x * NC;
    const int h = t >> 5;
    const int lane = t & 31;
    float y = g_x[off + t] + g_ffout[off + t];
    float s1 = y, s2 = y * y;
    #pragma unroll
    for (int s = 16; s > 0; s >>= 1) {
        s1 += __shfl_xor_sync(0xffffffffu, s1, s);
        s2 += __shfl_xor_sync(0xffffffffu, s2, s);
    }
    if (lane == 0) { r1[h] = s1; r2[h] = s2; }
    __syncthreads();
    if (t == 0) {
        float a = 0.f, c2 = 0.f;
        #pragma unroll
        for (int i = 0; i < 8; i++) { a += r1[i]; c2 += r2[i]; }
        r1[0] = a; r2[0] = c2;
    }
    __syncthreads();
    float mean = r1[0] * (1.0f / NC);
    float var  = r2[0] * (1.0f / NC) - mean * mean;
    out[off + t] = (y - mean) * rsqrtf(var + LN_EPS) * gamma[t] + beta[t];
}

// ======================= launch =============================================
extern "C" void kernel_launch(void* const* d_in, const int* in_sizes, int n_in,
                              void* d_out, int out_size) {
    const float* q     = (const float*)d_in[0];
    const float* kv    = (const float*)d_in[1];
    const float* wq_w  = (const float*)d_in[2];
    const float* wq_b  = (const float*)d_in[3];
    const float* wk_w  = (const float*)d_in[4];
    const float* wk_b  = (const float*)d_in[5];
    const float* wv_w  = (const float*)d_in[6];
    const float* wv_b  = (const float*)d_in[7];
    const float* ln1_g = (const float*)d_in[8];
    const float* ln1_b = (const float*)d_in[9];
    const float* ff1_w = (const float*)d_in[10];
    const float* ff1_b = (const float*)d_in[11];
    const float* ff2_w = (const float*)d_in[12];
    const float* ff2_b = (const float*)d_in[13];
    const float* ln2_g = (const float*)d_in[14];
    const float* ln2_b = (const float*)d_in[15];
    float* out = (float*)d_out;

    void *pQ, *pK, *pV, *pF;
    void *pqh, *pql, *pkh, *pkl, *pxh, *pxl, *phh, *phl;
    void *wqh, *wql, *wkh, *wkl, *wvh, *wvl, *f1h, *f1l, *f2h, *f2l;
    cudaGetSymbolAddress(&pQ, g_Qp);   cudaGetSymbolAddress(&pK, g_Kp);
    cudaGetSymbolAddress(&pV, g_Vp);   cudaGetSymbolAddress(&pF, g_ffout);
    cudaGetSymbolAddress(&pqh, g_qhi); cudaGetSymbolAddress(&pql, g_qlo);
    cudaGetSymbolAddress(&pkh, g_kvhi);cudaGetSymbolAddress(&pkl, g_kvlo);
    cudaGetSymbolAddress(&pxh, g_xhi); cudaGetSymbolAddress(&pxl, g_xlo);
    cudaGetSymbolAddress(&phh, g_hhi); cudaGetSymbolAddress(&phl, g_hlo);
    cudaGetSymbolAddress(&wqh, g_wqThi); cudaGetSymbolAddress(&wql, g_wqTlo);
    cudaGetSymbolAddress(&wkh, g_wkThi); cudaGetSymbolAddress(&wkl, g_wkTlo);
    cudaGetSymbolAddress(&wvh, g_wvThi); cudaGetSymbolAddress(&wvl, g_wvTlo);
    cudaGetSymbolAddress(&f1h, g_f1Thi); cudaGetSymbolAddress(&f1l, g_f1Tlo);
    cudaGetSymbolAddress(&f2h, g_f2Thi); cudaGetSymbolAddress(&f2l, g_f2Tlo);

    cudaFuncSetAttribute(tc_gemm<0>, cudaFuncAttributeMaxDynamicSharedMemorySize, GEMM_SMEM);
    cudaFuncSetAttribute(tc_gemm<1>, cudaFuncAttributeMaxDynamicSharedMemorySize, GEMM_SMEM);

    // input conversions
    const int convGrid = (int)(((size_t)NROWS * NC / 4) / 256);
    conv_split_kernel<<<convGrid, 256>>>(q,  (__nv_bfloat16*)pqh, (__nv_bfloat16*)pql);
    conv_split_kernel<<<convGrid, 256>>>(kv, (__nv_bfloat16*)pkh, (__nv_bfloat16*)pkl);
    dim3 tb(32, 8);
    convT_split_kernel<<<dim3(NC/32, NC/32), tb>>>(wq_w, (__nv_bfloat16*)wqh, (__nv_bfloat16*)wql, NC, NC);
    convT_split_kernel<<<dim3(NC/32, NC/32), tb>>>(wk_w, (__nv_bfloat16*)wkh, (__nv_bfloat16*)wkl, NC, NC);
    convT_split_kernel<<<dim3(NC/32, NC/32), tb>>>(wv_w, (__nv_bfloat16*)wvh, (__nv_bfloat16*)wvl, NC, NC);
    convT_split_kernel<<<dim3(FFDIM/32, NC/32), tb>>>(ff1_w, (__nv_bfloat16*)f1h, (__nv_bfloat16*)f1l, NC, FFDIM);
    convT_split_kernel<<<dim3(NC/32, FFDIM/32), tb>>>(ff2_w, (__nv_bfloat16*)f2h, (__nv_bfloat16*)f2l, FFDIM, NC);

    // QKV projections
    dim3 gQKV(NC / 128, NROWS / 128);
    tc_gemm<0><<<gQKV, 256, GEMM_SMEM>>>((__nv_bfloat16*)pqh, (__nv_bfloat16*)pql,
        (__nv_bfloat16*)wqh, (__nv_bfloat16*)wql, wq_b, (float*)pQ, 0, 0, NC, NC);
    tc_gemm<0><<<gQKV, 256, GEMM_SMEM>>>((__nv_bfloat16*)pkh, (__nv_bfloat16*)pkl,
        (__nv_bfloat16*)wkh, (__nv_bfloat16*)wkl, wk_b, (float*)pK, 0, 0, NC, NC);
    tc_gemm<0><<<gQKV, 256, GEMM_SMEM>>>((__nv_bfloat16*)pkh, (__nv_bfloat16*)pkl,
        (__nv_bfloat16*)wvh, (__nv_bfloat16*)wvl, wv_b, (float*)pV, 0, 0, NC, NC);

    // attention middle
    colmax_part_kernel<<<BATCH * (NSEQ / 256), 256>>>();
    colmax_red_kernel<<<BATCH, 256>>>();
    ctx_part_kernel<<<dim3(NSPLIT, BATCH * NHEADS), 256>>>();
    ctx_reduce_kernel<<<BATCH * NHEADS, DH * DH>>>();
    attn_ln1_kernel<<<NROWS / ROWS_PER_BLK, 256>>>(q, ln1_g, ln1_b);

    // FF
    dim3 gFF1(FFDIM / 128, NROWS / 128);
    tc_gemm<1><<<gFF1, 256, GEMM_SMEM>>>((__nv_bfloat16*)pxh, (__nv_bfloat16*)pxl,
        (__nv_bfloat16*)f1h, (__nv_bfloat16*)f1l, ff1_b, 0,
        (__nv_bfloat16*)phh, (__nv_bfloat16*)phl, FFDIM, NC);
    dim3 gFF2(NC / 128, NROWS / 128);
    tc_gemm<0><<<gFF2, 256, GEMM_SMEM>>>((__nv_bfloat16*)phh, (__nv_bfloat16*)phl,
        (__nv_bfloat16*)f2h, (__nv_bfloat16*)f2l, ff2_b, (float*)pF, 0, 0, NC, FFDIM);

    ln2_kernel<<<NROWS, 256>>>(ln2_g, ln2_b, out);
}

// round 5
// speedup vs baseline: 2.5216x; 1.2774x over previous
#include <cuda_runtime.h>
#include <cuda_fp16.h>
#include <math.h>
#include <stdint.h>

// Problem constants
#define BATCH   2
#define NSEQ    32768          // H*W*D
#define NC      256
#define NHEADS  8
#define DH      32
#define NROWS   (BATCH*NSEQ)   // 65536
#define FFDIM   1024
#define LN_EPS  1e-3f
#define NSPLIT  32

// ---------------- scratch (static __device__, no allocation) ----------------
__device__ __half g_Qp[(size_t)NROWS * NC];       // Q projection (fp16)
__device__ __half g_Kp[(size_t)NROWS * NC];       // K projection (fp16)
__device__ __half g_Vp[(size_t)NROWS * NC];       // V projection (fp16)
__device__ float  g_x [(size_t)NROWS * NC];       // LN1 output (fp32, residual)
__device__ __half g_ffout[(size_t)NROWS * NC];    // FF2 output (fp16)
__device__ float  g_partmax[(BATCH * (NSEQ/256)) * NC];
__device__ float  g_colmax[BATCH * NC];
__device__ float  g_Spart[(size_t)BATCH * NHEADS * NSPLIT * DH * DH];
__device__ float  g_Zpart[(size_t)BATCH * NHEADS * NSPLIT * DH];
__device__ float  g_ctx[BATCH * NHEADS * DH * DH];

// fp16 activations (hi only — GEMM corrects the weight side)
__device__ __half g_qh [(size_t)NROWS * NC];
__device__ __half g_kvh[(size_t)NROWS * NC];
__device__ __half g_xh [(size_t)NROWS * NC];
__device__ __half g_hh [(size_t)NROWS * FFDIM];
// transposed weights [N][K], fp16 hi + lo (2-term split => exact weights)
__device__ __half g_wqThi[NC*NC],    g_wqTlo[NC*NC];
__device__ __half g_wkThi[NC*NC],    g_wkTlo[NC*NC];
__device__ __half g_wvThi[NC*NC],    g_wvTlo[NC*NC];
__device__ __half g_f1Thi[FFDIM*NC], g_f1Tlo[FFDIM*NC];
__device__ __half g_f2Thi[NC*FFDIM], g_f2Tlo[NC*FFDIM];

// ======================= baseline-PTX helpers ===============================
__device__ __forceinline__ uint32_t smem_u32(const void* p) {
    uint32_t a;
    asm("{ .reg .u64 t; cvta.to.shared.u64 t, %1; cvt.u32.u64 %0, t; }" : "=r"(a) : "l"(p));
    return a;
}
__device__ __forceinline__ void ldsm4(uint32_t* r, uint32_t addr) {
    asm volatile("ldmatrix.sync.aligned.m8n8.x4.shared.b16 {%0,%1,%2,%3}, [%4];"
        : "=r"(r[0]), "=r"(r[1]), "=r"(r[2]), "=r"(r[3]) : "r"(addr));
}
__device__ __forceinline__ void mma16816(float* c, const uint32_t* a, const uint32_t* b) {
    asm volatile("mma.sync.aligned.m16n8k16.row.col.f32.f16.f16.f32 "
        "{%0,%1,%2,%3}, {%4,%5,%6,%7}, {%8,%9}, {%0,%1,%2,%3};"
        : "+f"(c[0]), "+f"(c[1]), "+f"(c[2]), "+f"(c[3])
        : "r"(a[0]), "r"(a[1]), "r"(a[2]), "r"(a[3]), "r"(b[0]), "r"(b[1]));
}
#define CP16(dst, src) \
    asm volatile("cp.async.cg.shared.global [%0], [%1], 16;" :: "r"(dst), "l"(src))
#define CP_COMMIT()  asm volatile("cp.async.commit_group;" ::: "memory")
#define CP_WAIT1()   asm volatile("cp.async.wait_group 1;" ::: "memory")
#define CP_WAIT0()   asm volatile("cp.async.wait_group 0;" ::: "memory")

__device__ __forceinline__ float gelu_exact(float v) {
    return 0.5f * v * (1.0f + erff(v * 0.70710678118654752440f));
}

// ======================= HMMA 2-term fp16 GEMM ==============================
// C[M,N] = A[M,K] @ W[K,N]; A fp16 [M][K]; W as hi/lo fp16 [N][K].
// A*(Whi+Wlo) = A*W exactly; only activation fp16 rounding remains (~1.4e-4).
// CTA tile 128x128, k-chunk 64, 8 warps (warp tile 64x32), double buffered.
#define KCH   64
#define BSTR  72                       // padded smem stride in halves
#define BSTRB (BSTR*2)                 // 144 bytes
#define TILEB (128*BSTRB)              // 18432 bytes per tile
#define SOFF(s, t) (((s)*3 + (t)) * TILEB)
#define GEMM_SMEM (6 * TILEB)          // 110592

__device__ __forceinline__ void load_tile(const __half* __restrict__ src,
                                          uint32_t dstbase, int row0, int col0,
                                          int ldk, int tid) {
    const __half* s = src + (size_t)(row0 + (tid >> 3)) * ldk + col0 + (tid & 7) * 8;
    uint32_t d = dstbase + (uint32_t)(tid >> 3) * BSTRB + (uint32_t)(tid & 7) * 16;
    #pragma unroll
    for (int p = 0; p < 4; p++)
        CP16(d + p * 32 * BSTRB, s + (size_t)p * 32 * ldk);
}

template<int EPI>  // 0: bias -> fp16 out.  1: bias + gelu -> fp16 out.
__global__ __launch_bounds__(256)
void tc_gemm(const __half* __restrict__ A,
             const __half* __restrict__ Bhi, const __half* __restrict__ Blo,
             const float* __restrict__ bias, __half* __restrict__ C,
             int N, int K) {
    extern __shared__ __align__(1024) char smem[];
    const uint32_t sb = smem_u32(smem);
    const int tid  = threadIdx.x;
    const int wid  = tid >> 5;
    const int lane = tid & 31;
    const int wm = wid & 1;            // 2 row groups of 64
    const int wn = wid >> 1;           // 4 col groups of 32
    const int rowA0 = blockIdx.y * 128;
    const int rowB0 = blockIdx.x * 128;
    const int nch = K / KCH;

    const int row_a  = (lane & 7) + ((lane >> 3) & 1) * 8;
    const int kcol_a = (lane >> 4) * 8;
    const uint32_t aoff = (uint32_t)(wm * 64 + row_a) * BSTRB + kcol_a * 2;
    const int row_b  = (lane & 7) + (lane >> 4) * 8;
    const int kcol_b = ((lane >> 3) & 1) * 8;
    const uint32_t boff = (uint32_t)(wn * 32 + row_b) * BSTRB + kcol_b * 2;

    float c[4][4][4];
    #pragma unroll
    for (int i = 0; i < 4; i++)
        #pragma unroll
        for (int j = 0; j < 4; j++)
            #pragma unroll
            for (int q = 0; q < 4; q++) c[i][j][q] = 0.0f;

    load_tile(A,   sb + SOFF(0, 0), rowA0, 0, K, tid);
    load_tile(Bhi, sb + SOFF(0, 1), rowB0, 0, K, tid);
    load_tile(Blo, sb + SOFF(0, 2), rowB0, 0, K, tid);
    CP_COMMIT();

    for (int ch = 0; ch < nch; ch++) {
        const int s = ch & 1;
        if (ch + 1 < nch) {
            const int ns = (ch + 1) & 1;
            const int col0 = (ch + 1) * KCH;
            load_tile(A,   sb + SOFF(ns, 0), rowA0, col0, K, tid);
            load_tile(Bhi, sb + SOFF(ns, 1), rowB0, col0, K, tid);
            load_tile(Blo, sb + SOFF(ns, 2), rowB0, col0, K, tid);
            CP_COMMIT();
            CP_WAIT1();
        } else {
            CP_WAIT0();
        }
        __syncthreads();

        const uint32_t aP = sb + SOFF(s, 0) + aoff;
        const uint32_t bH = sb + SOFF(s, 1) + boff;
        const uint32_t bL = sb + SOFF(s, 2) + boff;

        #pragma unroll
        for (int ks = 0; ks < KCH / 16; ks++) {
            uint32_t a[4][4], bhi[4][2], blo[4][2];
            #pragma unroll
            for (int mt = 0; mt < 4; mt++)
                ldsm4(a[mt], aP + mt * 16 * BSTRB + ks * 32);
            #pragma unroll
            for (int nt2 = 0; nt2 < 2; nt2++) {
                uint32_t r[4];
                ldsm4(r, bH + nt2 * 16 * BSTRB + ks * 32);
                bhi[nt2 * 2 + 0][0] = r[0]; bhi[nt2 * 2 + 0][1] = r[1];
                bhi[nt2 * 2 + 1][0] = r[2]; bhi[nt2 * 2 + 1][1] = r[3];
                ldsm4(r, bL + nt2 * 16 * BSTRB + ks * 32);
                blo[nt2 * 2 + 0][0] = r[0]; blo[nt2 * 2 + 0][1] = r[1];
                blo[nt2 * 2 + 1][0] = r[2]; blo[nt2 * 2 + 1][1] = r[3];
            }
            #pragma unroll
            for (int mt = 0; mt < 4; mt++)
                #pragma unroll
                for (int nt = 0; nt < 4; nt++) {
                    mma16816(c[mt][nt], a[mt], bhi[nt]);
                    mma16816(c[mt][nt], a[mt], blo[nt]);
                }
        }
        __syncthreads();
    }

    // ---- epilogue: bias (+gelu) -> fp16 ----
    const int mrow = blockIdx.y * 128 + wm * 64 + (lane >> 2);
    const int ncol = blockIdx.x * 128 + wn * 32 + 2 * (lane & 3);
    #pragma unroll
    for (int mt = 0; mt < 4; mt++) {
        #pragma unroll
        for (int nt = 0; nt < 4; nt++) {
            const int col = ncol + nt * 8;
            const float b0 = bias[col], b1 = bias[col + 1];
            #pragma unroll
            for (int half_ = 0; half_ < 2; half_++) {
                const int row = mrow + mt * 16 + half_ * 8;
                float v0 = c[mt][nt][half_ * 2 + 0] + b0;
                float v1 = c[mt][nt][half_ * 2 + 1] + b1;
                if (EPI == 1) { v0 = gelu_exact(v0); v1 = gelu_exact(v1); }
                *(__half2*)(C + (size_t)row * N + col) = __floats2half2_rn(v0, v1);
            }
        }
    }
}

// ======================= conversion kernels =================================
__global__ void conv_half_kernel(const float* __restrict__ x,
                                 __half* __restrict__ hi) {
    size_t i = ((size_t)blockIdx.x * blockDim.x + threadIdx.x) * 4;
    float4 v = *(const float4*)(x + i);
    __half2 a = __floats2half2_rn(v.x, v.y);
    __half2 b = __floats2half2_rn(v.z, v.w);
    *(uint2*)(hi + i) = make_uint2(*(uint32_t*)&a, *(uint32_t*)&b);
}

// W[K][N] fp32 -> WT[N][K] fp16 hi/lo
__global__ void convT_split_kernel(const float* __restrict__ W,
                                   __half* __restrict__ thi,
                                   __half* __restrict__ tlo, int K, int N) {
    __shared__ float t[32][33];
    const int n0 = blockIdx.x * 32, k0 = blockIdx.y * 32;
    const int tx = threadIdx.x, ty = threadIdx.y;
    for (int i = ty; i < 32; i += 8) t[i][tx] = W[(size_t)(k0 + i) * N + n0 + tx];
    __syncthreads();
    for (int i = ty; i < 32; i += 8) {
        float v = t[tx][i];
        size_t o = (size_t)(n0 + i) * K + k0 + tx;
        __half h = __float2half_rn(v);
        thi[o] = h;
        tlo[o] = __float2half_rn(v - __half2float(h));
    }
}

// ======================= attention middle ===================================
__global__ void colmax_part_kernel() {
    const int chunk = blockIdx.x;
    const int b = chunk / (NSEQ / 256);
    const int r0 = (chunk % (NSEQ / 256)) * 256;
    const int c = threadIdx.x;
    const __half* base = g_Kp + ((size_t)b * NSEQ + r0) * NC;
    float m = -INFINITY;
    for (int r = 0; r < 256; r++)
        m = fmaxf(m, __half2float(base[(size_t)r * NC + c]));
    g_partmax[(size_t)chunk * NC + c] = m;
}
__global__ void colmax_red_kernel() {
    const int b = blockIdx.x;
    const int c = threadIdx.x;
    float m = -INFINITY;
    for (int ch = 0; ch < NSEQ / 256; ch++)
        m = fmaxf(m, g_partmax[((size_t)(b * (NSEQ / 256) + ch)) * NC + c]);
    g_colmax[b * NC + c] = m;
}
__global__ __launch_bounds__(256)
void ctx_part_kernel() {
    const int s  = blockIdx.x;
    const int bh = blockIdx.y;
    const int b = bh / NHEADS;
    const int h = bh % NHEADS;
    const int t = threadIdx.x;
    const int chunk = NSEQ / NSPLIT;
    __shared__ float ek[8][DH];
    __shared__ float vv[8][DH];
    const int e  = t & 31;
    const int d0 = (t >> 5) * 4;
    float acc0 = 0.f, acc1 = 0.f, acc2 = 0.f, acc3 = 0.f, zacc = 0.f;
    for (int g = 0; g < chunk / 8; g++) {
        #pragma unroll
        for (int i = 0; i < 2; i++) {
            int idx = t + i * 256;
            int row = idx >> 6;
            int col = idx & 63;
            int n = s * chunk + g * 8 + row;
            size_t base = ((size_t)b * NSEQ + n) * NC + h * DH;
            if (col < DH) {
                float kv = __half2float(g_Kp[base + col]);
                ek[row][col] = expf(kv - g_colmax[b * NC + h * DH + col]);
            } else {
                vv[row][col - DH] = __half2float(g_Vp[base + (col - DH)]);
            }
        }
        __syncthreads();
        #pragma unroll
        for (int row = 0; row < 8; row++) {
            float v = vv[row][e];
            acc0 = fmaf(ek[row][d0 + 0], v, acc0);
            acc1 = fmaf(ek[row][d0 + 1], v, acc1);
            acc2 = fmaf(ek[row][d0 + 2], v, acc2);
            acc3 = fmaf(ek[row][d0 + 3], v, acc3);
        }
        if (t < DH) {
            #pragma unroll
            for (int row = 0; row < 8; row++) zacc += ek[row][t];
        }
        __syncthreads();
    }
    const size_t sp = ((size_t)bh * NSPLIT + s) * (DH * DH);
    g_Spart[sp + (d0 + 0) * DH + e] = acc0;
    g_Spart[sp + (d0 + 1) * DH + e] = acc1;
    g_Spart[sp + (d0 + 2) * DH + e] = acc2;
    g_Spart[sp + (d0 + 3) * DH + e] = acc3;
    if (t < DH) g_Zpart[((size_t)bh * NSPLIT + s) * DH + t] = zacc;
}
__global__ void ctx_reduce_kernel() {
    const int bh = blockIdx.x;
    const int t = threadIdx.x;
    const int d = t >> 5;
    __shared__ float zs[DH];
    float ssum = 0.f;
    for (int p = 0; p < NSPLIT; p++)
        ssum += g_Spart[((size_t)bh * NSPLIT + p) * (DH * DH) + t];
    if (t < DH) {
        float z = 0.f;
        for (int p = 0; p < NSPLIT; p++)
            z += g_Zpart[((size_t)bh * NSPLIT + p) * DH + t];
        zs[t] = z;
    }
    __syncthreads();
    g_ctx[(size_t)bh * (DH * DH) + t] = ssum / zs[d];
}

// fused softmax(Q) -> attn -> +residual -> LN1 (emits fp32 x and fp16 x_hi)
#define ROWS_PER_BLK 16
__global__ __launch_bounds__(256)
void attn_ln1_kernel(const float* __restrict__ qin,
                     const float* __restrict__ gamma,
                     const float* __restrict__ beta) {
    __shared__ float ctxs[NHEADS * DH * DH];
    __shared__ float r1[8], r2[8];
    const int t = threadIdx.x;
    const int row0 = blockIdx.x * ROWS_PER_BLK;
    const int b = row0 / NSEQ;
    for (int i = t; i < NHEADS * DH * DH; i += 256)
        ctxs[i] = g_ctx[(size_t)b * NHEADS * DH * DH + i];
    __syncthreads();
    const int h = t >> 5;
    const int lane = t & 31;
    const float gc = gamma[t];
    const float bc = beta[t];
    for (int r = 0; r < ROWS_PER_BLK; r++) {
        const size_t off = (size_t)(row0 + r) * NC;
        float qv = __half2float(g_Qp[off + t]);
        float m = qv;
        #pragma unroll
        for (int s = 16; s > 0; s >>= 1) m = fmaxf(m, __shfl_xor_sync(0xffffffffu, m, s));
        float ev = expf(qv - m);
        float ss = ev;
        #pragma unroll
        for (int s = 16; s > 0; s >>= 1) ss += __shfl_xor_sync(0xffffffffu, ss, s);
        float qn = ev / ss;
        float acc = 0.f;
        #pragma unroll
        for (int d = 0; d < DH; d++) {
            float qd = __shfl_sync(0xffffffffu, qn, d);
            acc = fmaf(qd, ctxs[h * (DH * DH) + d * DH + lane], acc);
        }
        float y = qin[off + t] + acc;
        float s1 = y, s2 = y * y;
        #pragma unroll
        for (int s = 16; s > 0; s >>= 1) {
            s1 += __shfl_xor_sync(0xffffffffu, s1, s);
            s2 += __shfl_xor_sync(0xffffffffu, s2, s);
        }
        if (lane == 0) { r1[h] = s1; r2[h] = s2; }
        __syncthreads();
        if (t == 0) {
            float a = 0.f, c2 = 0.f;
            #pragma unroll
            for (int i = 0; i < 8; i++) { a += r1[i]; c2 += r2[i]; }
            r1[0] = a; r2[0] = c2;
        }
        __syncthreads();
        float mean = r1[0] * (1.0f / NC);
        float var  = r2[0] * (1.0f / NC) - mean * mean;
        float xv = (y - mean) * rsqrtf(var + LN_EPS) * gc + bc;
        g_x[off + t] = xv;
        g_xh[off + t] = __float2half_rn(xv);
        __syncthreads();
    }
}

__global__ __launch_bounds__(256)
void ln2_kernel(const float* __restrict__ gamma, const float* __restrict__ beta,
                float* __restrict__ out) {
    __shared__ float r1[8], r2[8];
    const int t = threadIdx.x;
    const size_t off = (size_t)blockIdx.x * NC;
    const int h = t >> 5;
    const int lane = t & 31;
    float y = g_x[off + t] + __half2float(g_ffout[off + t]);
    float s1 = y, s2 = y * y;
    #pragma unroll
    for (int s = 16; s > 0; s >>= 1) {
        s1 += __shfl_xor_sync(0xffffffffu, s1, s);
        s2 += __shfl_xor_sync(0xffffffffu, s2, s);
    }
    if (lane == 0) { r1[h] = s1; r2[h] = s2; }
    __syncthreads();
    if (t == 0) {
        float a = 0.f, c2 = 0.f;
        #pragma unroll
        for (int i = 0; i < 8; i++) { a += r1[i]; c2 += r2[i]; }
        r1[0] = a; r2[0] = c2;
    }
    __syncthreads();
    float mean = r1[0] * (1.0f / NC);
    float var  = r2[0] * (1.0f / NC) - mean * mean;
    out[off + t] = (y - mean) * rsqrtf(var + LN_EPS) * gamma[t] + beta[t];
}

// ======================= launch =============================================
extern "C" void kernel_launch(void* const* d_in, const int* in_sizes, int n_in,
                              void* d_out, int out_size) {
    const float* q     = (const float*)d_in[0];
    const float* kv    = (const float*)d_in[1];
    const float* wq_w  = (const float*)d_in[2];
    const float* wq_b  = (const float*)d_in[3];
    const float* wk_w  = (const float*)d_in[4];
    const float* wk_b  = (const float*)d_in[5];
    const float* wv_w  = (const float*)d_in[6];
    const float* wv_b  = (const float*)d_in[7];
    const float* ln1_g = (const float*)d_in[8];
    const float* ln1_b = (const float*)d_in[9];
    const float* ff1_w = (const float*)d_in[10];
    const float* ff1_b = (const float*)d_in[11];
    const float* ff2_w = (const float*)d_in[12];
    const float* ff2_b = (const float*)d_in[13];
    const float* ln2_g = (const float*)d_in[14];
    const float* ln2_b = (const float*)d_in[15];
    float* out = (float*)d_out;

    void *pQ, *pK, *pV, *pF;
    void *pqh, *pkvh, *pxh, *phh;
    void *wqh, *wql, *wkh, *wkl, *wvh, *wvl, *f1h, *f1l, *f2h, *f2l;
    cudaGetSymbolAddress(&pQ, g_Qp);    cudaGetSymbolAddress(&pK, g_Kp);
    cudaGetSymbolAddress(&pV, g_Vp);    cudaGetSymbolAddress(&pF, g_ffout);
    cudaGetSymbolAddress(&pqh, g_qh);   cudaGetSymbolAddress(&pkvh, g_kvh);
    cudaGetSymbolAddress(&pxh, g_xh);   cudaGetSymbolAddress(&phh, g_hh);
    cudaGetSymbolAddress(&wqh, g_wqThi); cudaGetSymbolAddress(&wql, g_wqTlo);
    cudaGetSymbolAddress(&wkh, g_wkThi); cudaGetSymbolAddress(&wkl, g_wkTlo);
    cudaGetSymbolAddress(&wvh, g_wvThi); cudaGetSymbolAddress(&wvl, g_wvTlo);
    cudaGetSymbolAddress(&f1h, g_f1Thi); cudaGetSymbolAddress(&f1l, g_f1Tlo);
    cudaGetSymbolAddress(&f2h, g_f2Thi); cudaGetSymbolAddress(&f2l, g_f2Tlo);

    cudaFuncSetAttribute(tc_gemm<0>, cudaFuncAttributeMaxDynamicSharedMemorySize, GEMM_SMEM);
    cudaFuncSetAttribute(tc_gemm<1>, cudaFuncAttributeMaxDynamicSharedMemorySize, GEMM_SMEM);

    // input conversions
    const int convGrid = (int)(((size_t)NROWS * NC / 4) / 256);
    conv_half_kernel<<<convGrid, 256>>>(q,  (__half*)pqh);
    conv_half_kernel<<<convGrid, 256>>>(kv, (__half*)pkvh);
    dim3 tb(32, 8);
    convT_split_kernel<<<dim3(NC/32, NC/32), tb>>>(wq_w, (__half*)wqh, (__half*)wql, NC, NC);
    convT_split_kernel<<<dim3(NC/32, NC/32), tb>>>(wk_w, (__half*)wkh, (__half*)wkl, NC, NC);
    convT_split_kernel<<<dim3(NC/32, NC/32), tb>>>(wv_w, (__half*)wvh, (__half*)wvl, NC, NC);
    convT_split_kernel<<<dim3(FFDIM/32, NC/32), tb>>>(ff1_w, (__half*)f1h, (__half*)f1l, NC, FFDIM);
    convT_split_kernel<<<dim3(NC/32, FFDIM/32), tb>>>(ff2_w, (__half*)f2h, (__half*)f2l, FFDIM, NC);

    // QKV projections
    dim3 gQKV(NC / 128, NROWS / 128);
    tc_gemm<0><<<gQKV, 256, GEMM_SMEM>>>((__half*)pqh,  (__half*)wqh, (__half*)wql, wq_b, (__half*)pQ, NC, NC);
    tc_gemm<0><<<gQKV, 256, GEMM_SMEM>>>((__half*)pkvh, (__half*)wkh, (__half*)wkl, wk_b, (__half*)pK, NC, NC);
    tc_gemm<0><<<gQKV, 256, GEMM_SMEM>>>((__half*)pkvh, (__half*)wvh, (__half*)wvl, wv_b, (__half*)pV, NC, NC);

    // attention middle
    colmax_part_kernel<<<BATCH * (NSEQ / 256), 256>>>();
    colmax_red_kernel<<<BATCH, 256>>>();
    ctx_part_kernel<<<dim3(NSPLIT, BATCH * NHEADS), 256>>>();
    ctx_reduce_kernel<<<BATCH * NHEADS, DH * DH>>>();
    attn_ln1_kernel<<<NROWS / ROWS_PER_BLK, 256>>>(q, ln1_g, ln1_b);

    // FF
    dim3 gFF1(FFDIM / 128, NROWS / 128);
    tc_gemm<1><<<gFF1, 256, GEMM_SMEM>>>((__half*)pxh, (__half*)f1h, (__half*)f1l, ff1_b, (__half*)phh, FFDIM, NC);
    dim3 gFF2(NC / 128, NROWS / 128);
    tc_gemm<0><<<gFF2, 256, GEMM_SMEM>>>((__half*)phh, (__half*)f2h, (__half*)f2l, ff2_b, (__half*)pF, NC, FFDIM);

    ln2_kernel<<<NROWS, 256>>>(ln2_g, ln2_b, out);
}

// round 7
// speedup vs baseline: 3.4066x; 1.3509x over previous
#include <cuda_runtime.h>
#include <cuda_fp16.h>
#include <math.h>
#include <stdint.h>

// Problem constants
#define BATCH   2
#define NSEQ    32768          // H*W*D
#define NC      256
#define NHEADS  8
#define DH      32
#define NROWS   (BATCH*NSEQ)   // 65536
#define FFDIM   1024
#define LN_EPS  1e-3f
#define NSPLIT  32

// ---------------- scratch (static __device__, no allocation) ----------------
__device__ __half g_Qp[(size_t)NROWS * NC];       // Q projection (fp16)
__device__ __half g_Kp[(size_t)NROWS * NC];       // K projection (fp16)
__device__ __half g_Vp[(size_t)NROWS * NC];       // V projection (fp16)
__device__ float  g_x [(size_t)NROWS * NC];       // LN1 output (fp32, residual)
__device__ __half g_ffout[(size_t)NROWS * NC];    // FF2 output (fp16)
__device__ float  g_partmax[(BATCH * (NSEQ/256)) * NC];
__device__ float  g_colmax[BATCH * NC];
__device__ float  g_Spart[(size_t)BATCH * NHEADS * NSPLIT * DH * DH];
__device__ float  g_Zpart[(size_t)BATCH * NHEADS * NSPLIT * DH];
__device__ float  g_ctx[BATCH * NHEADS * DH * DH];

// fp16 activations
__device__ __half g_qh [(size_t)NROWS * NC];
__device__ __half g_kvh[(size_t)NROWS * NC];
__device__ __half g_xh [(size_t)NROWS * NC];
__device__ __half g_hh [(size_t)NROWS * FFDIM];
// transposed weights [N][K], fp16
__device__ __half g_wqT[NC*NC];
__device__ __half g_wkT[NC*NC];
__device__ __half g_wvT[NC*NC];
__device__ __half g_f1T[FFDIM*NC];
__device__ __half g_f2T[NC*FFDIM];

// ======================= baseline-PTX helpers ===============================
__device__ __forceinline__ uint32_t smem_u32(const void* p) {
    uint32_t a;
    asm("{ .reg .u64 t; cvta.to.shared.u64 t, %1; cvt.u32.u64 %0, t; }" : "=r"(a) : "l"(p));
    return a;
}
__device__ __forceinline__ void ldsm4(uint32_t* r, uint32_t addr) {
    asm volatile("ldmatrix.sync.aligned.m8n8.x4.shared.b16 {%0,%1,%2,%3}, [%4];"
        : "=r"(r[0]), "=r"(r[1]), "=r"(r[2]), "=r"(r[3]) : "r"(addr));
}
__device__ __forceinline__ void mma16816(float* c, const uint32_t* a, const uint32_t* b) {
    asm volatile("mma.sync.aligned.m16n8k16.row.col.f32.f16.f16.f32 "
        "{%0,%1,%2,%3}, {%4,%5,%6,%7}, {%8,%9}, {%0,%1,%2,%3};"
        : "+f"(c[0]), "+f"(c[1]), "+f"(c[2]), "+f"(c[3])
        : "r"(a[0]), "r"(a[1]), "r"(a[2]), "r"(a[3]), "r"(b[0]), "r"(b[1]));
}
#define CP16(dst, src) \
    asm volatile("cp.async.cg.shared.global [%0], [%1], 16;" :: "r"(dst), "l"(src))
#define CP_COMMIT()  asm volatile("cp.async.commit_group;" ::: "memory")
#define CP_WAIT2()   asm volatile("cp.async.wait_group 2;" ::: "memory")
#define CP_WAIT1()   asm volatile("cp.async.wait_group 1;" ::: "memory")
#define CP_WAIT0()   asm volatile("cp.async.wait_group 0;" ::: "memory")

__device__ __forceinline__ float gelu_exact(float v) {
    return 0.5f * v * (1.0f + erff(v * 0.70710678118654752440f));
}

// ======================= HMMA fp16 GEMM =====================================
// C[M,N] = A[M,K] @ W[K,N]; A fp16 [M][K]; W fp16 [N][K] (transposed).
// CTA tile 128x128, k-chunk 64, 8 warps (warp tile 64x32),
// 3-stage cp.async pipeline, 2 CTAs/SM.
#define KCH   64
#define BSTR  72                       // padded smem stride in halves
#define BSTRB (BSTR*2)                 // 144 bytes
#define TILEB (128*BSTRB)              // 18432 bytes per tile
#define NSTAGE 3
#define SOFF(s, t) (((s)*2 + (t)) * TILEB)
#define GEMM_SMEM (NSTAGE * 2 * TILEB) // 110592

__device__ __forceinline__ void load_tile(const __half* __restrict__ src,
                                          uint32_t dstbase, int row0, int col0,
                                          int ldk, int tid) {
    const __half* s = src + (size_t)(row0 + (tid >> 3)) * ldk + col0 + (tid & 7) * 8;
    uint32_t d = dstbase + (uint32_t)(tid >> 3) * BSTRB + (uint32_t)(tid & 7) * 16;
    #pragma unroll
    for (int p = 0; p < 4; p++)
        CP16(d + p * 32 * BSTRB, s + (size_t)p * 32 * ldk);
}

template<int EPI>  // 0: bias -> fp16 out.  1: bias + gelu -> fp16 out.
__global__ __launch_bounds__(256, 2)
void tc_gemm(const __half* __restrict__ A, const __half* __restrict__ B,
             const float* __restrict__ bias, __half* __restrict__ C,
             int N, int K) {
    extern __shared__ __align__(1024) char smem[];
    const uint32_t sb = smem_u32(smem);
    const int tid  = threadIdx.x;
    const int wid  = tid >> 5;
    const int lane = tid & 31;
    const int wm = wid & 1;            // 2 row groups of 64
    const int wn = wid >> 1;           // 4 col groups of 32
    const int rowA0 = blockIdx.y * 128;
    const int rowB0 = blockIdx.x * 128;
    const int nch = K / KCH;

    const int row_a  = (lane & 7) + ((lane >> 3) & 1) * 8;
    const int kcol_a = (lane >> 4) * 8;
    const uint32_t aoff = (uint32_t)(wm * 64 + row_a) * BSTRB + kcol_a * 2;
    const int row_b  = (lane & 7) + (lane >> 4) * 8;
    const int kcol_b = ((lane >> 3) & 1) * 8;
    const uint32_t boff = (uint32_t)(wn * 32 + row_b) * BSTRB + kcol_b * 2;

    float c[4][4][4];
    #pragma unroll
    for (int i = 0; i < 4; i++)
        #pragma unroll
        for (int j = 0; j < 4; j++)
            #pragma unroll
            for (int q = 0; q < 4; q++) c[i][j][q] = 0.0f;

    // prologue: stages 0,1
    load_tile(A, sb + SOFF(0, 0), rowA0, 0, K, tid);
    load_tile(B, sb + SOFF(0, 1), rowB0, 0, K, tid);
    CP_COMMIT();
    if (nch > 1) {
        load_tile(A, sb + SOFF(1, 0), rowA0, KCH, K, tid);
        load_tile(B, sb + SOFF(1, 1), rowB0, KCH, K, tid);
        CP_COMMIT();
    }

    for (int ch = 0; ch < nch; ch++) {
        const int s = ch % NSTAGE;
        if (ch + 2 < nch) {
            const int ns = (ch + 2) % NSTAGE;
            const int col0 = (ch + 2) * KCH;
            load_tile(A, sb + SOFF(ns, 0), rowA0, col0, K, tid);
            load_tile(B, sb + SOFF(ns, 1), rowB0, col0, K, tid);
            CP_COMMIT();
            CP_WAIT2();
        } else if (ch + 1 < nch) {
            CP_WAIT1();
        } else {
            CP_WAIT0();
        }
        __syncthreads();

        const uint32_t aP = sb + SOFF(s, 0) + aoff;
        const uint32_t bP = sb + SOFF(s, 1) + boff;

        #pragma unroll
        for (int ks = 0; ks < KCH / 16; ks++) {
            uint32_t a[4][4], b[4][2];
            #pragma unroll
            for (int mt = 0; mt < 4; mt++)
                ldsm4(a[mt], aP + mt * 16 * BSTRB + ks * 32);
            #pragma unroll
            for (int nt2 = 0; nt2 < 2; nt2++) {
                uint32_t r[4];
                ldsm4(r, bP + nt2 * 16 * BSTRB + ks * 32);
                b[nt2 * 2 + 0][0] = r[0]; b[nt2 * 2 + 0][1] = r[1];
                b[nt2 * 2 + 1][0] = r[2]; b[nt2 * 2 + 1][1] = r[3];
            }
            #pragma unroll
            for (int mt = 0; mt < 4; mt++)
                #pragma unroll
                for (int nt = 0; nt < 4; nt++)
                    mma16816(c[mt][nt], a[mt], b[nt]);
        }
        __syncthreads();
    }

    // ---- epilogue: bias (+gelu) -> fp16 ----
    const int mrow = blockIdx.y * 128 + wm * 64 + (lane >> 2);
    const int ncol = blockIdx.x * 128 + wn * 32 + 2 * (lane & 3);
    #pragma unroll
    for (int mt = 0; mt < 4; mt++) {
        #pragma unroll
        for (int nt = 0; nt < 4; nt++) {
            const int col = ncol + nt * 8;
            const float b0 = bias[col], b1 = bias[col + 1];
            #pragma unroll
            for (int half_ = 0; half_ < 2; half_++) {
                const int row = mrow + mt * 16 + half_ * 8;
                float v0 = c[mt][nt][half_ * 2 + 0] + b0;
                float v1 = c[mt][nt][half_ * 2 + 1] + b1;
                if (EPI == 1) { v0 = gelu_exact(v0); v1 = gelu_exact(v1); }
                *(__half2*)(C + (size_t)row * N + col) = __floats2half2_rn(v0, v1);
            }
        }
    }
}

// ======================= conversion kernels =================================
__global__ void conv_half_kernel(const float* __restrict__ x,
                                 __half* __restrict__ hi) {
    size_t i = ((size_t)blockIdx.x * blockDim.x + threadIdx.x) * 4;
    float4 v = *(const float4*)(x + i);
    __half2 a = __floats2half2_rn(v.x, v.y);
    __half2 b = __floats2half2_rn(v.z, v.w);
    *(uint2*)(hi + i) = make_uint2(*(uint32_t*)&a, *(uint32_t*)&b);
}

// W[K][N] fp32 -> WT[N][K] fp16
__global__ void convT_kernel(const float* __restrict__ W,
                             __half* __restrict__ tW, int K, int N) {
    __shared__ float t[32][33];
    const int n0 = blockIdx.x * 32, k0 = blockIdx.y * 32;
    const int tx = threadIdx.x, ty = threadIdx.y;
    for (int i = ty; i < 32; i += 8) t[i][tx] = W[(size_t)(k0 + i) * N + n0 + tx];
    __syncthreads();
    for (int i = ty; i < 32; i += 8)
        tW[(size_t)(n0 + i) * K + k0 + tx] = __float2half_rn(t[tx][i]);
}

// ======================= attention middle ===================================
__global__ void colmax_part_kernel() {
    const int chunk = blockIdx.x;
    const int b = chunk / (NSEQ / 256);
    const int r0 = (chunk % (NSEQ / 256)) * 256;
    const int c = threadIdx.x;
    const __half* base = g_Kp + ((size_t)b * NSEQ + r0) * NC;
    float m = -INFINITY;
    for (int r = 0; r < 256; r++)
        m = fmaxf(m, __half2float(base[(size_t)r * NC + c]));
    g_partmax[(size_t)chunk * NC + c] = m;
}
__global__ void colmax_red_kernel() {
    const int b = blockIdx.x;
    const int c = threadIdx.x;
    float m = -INFINITY;
    for (int ch = 0; ch < NSEQ / 256; ch++)
        m = fmaxf(m, g_partmax[((size_t)(b * (NSEQ / 256) + ch)) * NC + c]);
    g_colmax[b * NC + c] = m;
}
__global__ __launch_bounds__(256)
void ctx_part_kernel() {
    const int s  = blockIdx.x;
    const int bh = blockIdx.y;
    const int b = bh / NHEADS;
    const int h = bh % NHEADS;
    const int t = threadIdx.x;
    const int chunk = NSEQ / NSPLIT;
    __shared__ float ek[8][DH];
    __shared__ float vv[8][DH];
    const int e  = t & 31;
    const int d0 = (t >> 5) * 4;
    float acc0 = 0.f, acc1 = 0.f, acc2 = 0.f, acc3 = 0.f, zacc = 0.f;
    for (int g = 0; g < chunk / 8; g++) {
        #pragma unroll
        for (int i = 0; i < 2; i++) {
            int idx = t + i * 256;
            int row = idx >> 6;
            int col = idx & 63;
            int n = s * chunk + g * 8 + row;
            size_t base = ((size_t)b * NSEQ + n) * NC + h * DH;
            if (col < DH) {
                float kv = __half2float(g_Kp[base + col]);
                ek[row][col] = expf(kv - g_colmax[b * NC + h * DH + col]);
            } else {
                vv[row][col - DH] = __half2float(g_Vp[base + (col - DH)]);
            }
        }
        __syncthreads();
        #pragma unroll
        for (int row = 0; row < 8; row++) {
            float v = vv[row][e];
            acc0 = fmaf(ek[row][d0 + 0], v, acc0);
            acc1 = fmaf(ek[row][d0 + 1], v, acc1);
            acc2 = fmaf(ek[row][d0 + 2], v, acc2);
            acc3 = fmaf(ek[row][d0 + 3], v, acc3);
        }
        if (t < DH) {
            #pragma unroll
            for (int row = 0; row < 8; row++) zacc += ek[row][t];
        }
        __syncthreads();
    }
    const size_t sp = ((size_t)bh * NSPLIT + s) * (DH * DH);
    g_Spart[sp + (d0 + 0) * DH + e] = acc0;
    g_Spart[sp + (d0 + 1) * DH + e] = acc1;
    g_Spart[sp + (d0 + 2) * DH + e] = acc2;
    g_Spart[sp + (d0 + 3) * DH + e] = acc3;
    if (t < DH) g_Zpart[((size_t)bh * NSPLIT + s) * DH + t] = zacc;
}
__global__ void ctx_reduce_kernel() {
    const int bh = blockIdx.x;
    const int t = threadIdx.x;
    const int d = t >> 5;
    __shared__ float zs[DH];
    float ssum = 0.f;
    for (int p = 0; p < NSPLIT; p++)
        ssum += g_Spart[((size_t)bh * NSPLIT + p) * (DH * DH) + t];
    if (t < DH) {
        float z = 0.f;
        for (int p = 0; p < NSPLIT; p++)
            z += g_Zpart[((size_t)bh * NSPLIT + p) * DH + t];
        zs[t] = z;
    }
    __syncthreads();
    g_ctx[(size_t)bh * (DH * DH) + t] = ssum / zs[d];
}

// fused softmax(Q) -> attn -> +residual -> LN1 (emits fp32 x and fp16 x_hi)
#define ROWS_PER_BLK 16
__global__ __launch_bounds__(256)
void attn_ln1_kernel(const float* __restrict__ qin,
                     const float* __restrict__ gamma,
                     const float* __restrict__ beta) {
    __shared__ float ctxs[NHEADS * DH * DH];
    __shared__ float r1[8], r2[8];
    const int t = threadIdx.x;
    const int row0 = blockIdx.x * ROWS_PER_BLK;
    const int b = row0 / NSEQ;
    for (int i = t; i < NHEADS * DH * DH; i += 256)
        ctxs[i] = g_ctx[(size_t)b * NHEADS * DH * DH + i];
    __syncthreads();
    const int h = t >> 5;
    const int lane = t & 31;
    const float gc = gamma[t];
    const float bc = beta[t];
    for (int r = 0; r < ROWS_PER_BLK; r++) {
        const size_t off = (size_t)(row0 + r) * NC;
        float qv = __half2float(g_Qp[off + t]);
        float m = qv;
        #pragma unroll
        for (int s = 16; s > 0; s >>= 1) m = fmaxf(m, __shfl_xor_sync(0xffffffffu, m, s));
        float ev = expf(qv - m);
        float ss = ev;
        #pragma unroll
        for (int s = 16; s > 0; s >>= 1) ss += __shfl_xor_sync(0xffffffffu, ss, s);
        float qn = ev / ss;
        float acc = 0.f;
        #pragma unroll
        for (int d = 0; d < DH; d++) {
            float qd = __shfl_sync(0xffffffffu, qn, d);
            acc = fmaf(qd, ctxs[h * (DH * DH) + d * DH + lane], acc);
        }
        float y = qin[off + t] + acc;
        float s1 = y, s2 = y * y;
        #pragma unroll
        for (int s = 16; s > 0; s >>= 1) {
            s1 += __shfl_xor_sync(0xffffffffu, s1, s);
            s2 += __shfl_xor_sync(0xffffffffu, s2, s);
        }
        if (lane == 0) { r1[h] = s1; r2[h] = s2; }
        __syncthreads();
        if (t == 0) {
            float a = 0.f, c2 = 0.f;
            #pragma unroll
            for (int i = 0; i < 8; i++) { a += r1[i]; c2 += r2[i]; }
            r1[0] = a; r2[0] = c2;
        }
        __syncthreads();
        float mean = r1[0] * (1.0f / NC);
        float var  = r2[0] * (1.0f / NC) - mean * mean;
        float xv = (y - mean) * rsqrtf(var + LN_EPS) * gc + bc;
        g_x[off + t] = xv;
        g_xh[off + t] = __float2half_rn(xv);
        __syncthreads();
    }
}

__global__ __launch_bounds__(256)
void ln2_kernel(const float* __restrict__ gamma, const float* __restrict__ beta,
                float* __restrict__ out) {
    __shared__ float r1[8], r2[8];
    const int t = threadIdx.x;
    const size_t off = (size_t)blockIdx.x * NC;
    const int h = t >> 5;
    const int lane = t & 31;
    float y = g_x[off + t] + __half2float(g_ffout[off + t]);
    float s1 = y, s2 = y * y;
    #pragma unroll
    for (int s = 16; s > 0; s >>= 1) {
        s1 += __shfl_xor_sync(0xffffffffu, s1, s);
        s2 += __shfl_xor_sync(0xffffffffu, s2, s);
    }
    if (lane == 0) { r1[h] = s1; r2[h] = s2; }
    __syncthreads();
    if (t == 0) {
        float a = 0.f, c2 = 0.f;
        #pragma unroll
        for (int i = 0; i < 8; i++) { a += r1[i]; c2 += r2[i]; }
        r1[0] = a; r2[0] = c2;
    }
    __syncthreads();
    float mean = r1[0] * (1.0f / NC);
    float var  = r2[0] * (1.0f / NC) - mean * mean;
    out[off + t] = (y - mean) * rsqrtf(var + LN_EPS) * gamma[t] + beta[t];
}

// ======================= launch =============================================
extern "C" void kernel_launch(void* const* d_in, const int* in_sizes, int n_in,
                              void* d_out, int out_size) {
    const float* q     = (const float*)d_in[0];
    const float* kv    = (const float*)d_in[1];
    const float* wq_w  = (const float*)d_in[2];
    const float* wq_b  = (const float*)d_in[3];
    const float* wk_w  = (const float*)d_in[4];
    const float* wk_b  = (const float*)d_in[5];
    const float* wv_w  = (const float*)d_in[6];
    const float* wv_b  = (const float*)d_in[7];
    const float* ln1_g = (const float*)d_in[8];
    const float* ln1_b = (const float*)d_in[9];
    const float* ff1_w = (const float*)d_in[10];
    const float* ff1_b = (const float*)d_in[11];
    const float* ff2_w = (const float*)d_in[12];
    const float* ff2_b = (const float*)d_in[13];
    const float* ln2_g = (const float*)d_in[14];
    const float* ln2_b = (const float*)d_in[15];
    float* out = (float*)d_out;

    void *pQ, *pK, *pV, *pF;
    void *pqh, *pkvh, *pxh, *phh;
    void *wq, *wk, *wv, *f1, *f2;
    cudaGetSymbolAddress(&pQ, g_Qp);    cudaGetSymbolAddress(&pK, g_Kp);
    cudaGetSymbolAddress(&pV, g_Vp);    cudaGetSymbolAddress(&pF, g_ffout);
    cudaGetSymbolAddress(&pqh, g_qh);   cudaGetSymbolAddress(&pkvh, g_kvh);
    cudaGetSymbolAddress(&pxh, g_xh);   cudaGetSymbolAddress(&phh, g_hh);
    cudaGetSymbolAddress(&wq, g_wqT);   cudaGetSymbolAddress(&wk, g_wkT);
    cudaGetSymbolAddress(&wv, g_wvT);   cudaGetSymbolAddress(&f1, g_f1T);
    cudaGetSymbolAddress(&f2, g_f2T);

    cudaFuncSetAttribute(tc_gemm<0>, cudaFuncAttributeMaxDynamicSharedMemorySize, GEMM_SMEM);
    cudaFuncSetAttribute(tc_gemm<1>, cudaFuncAttributeMaxDynamicSharedMemorySize, GEMM_SMEM);

    // input conversions
    const int convGrid = (int)(((size_t)NROWS * NC / 4) / 256);
    conv_half_kernel<<<convGrid, 256>>>(q,  (__half*)pqh);
    conv_half_kernel<<<convGrid, 256>>>(kv, (__half*)pkvh);
    dim3 tb(32, 8);
    convT_kernel<<<dim3(NC/32, NC/32), tb>>>(wq_w, (__half*)wq, NC, NC);
    convT_kernel<<<dim3(NC/32, NC/32), tb>>>(wk_w, (__half*)wk, NC, NC);
    convT_kernel<<<dim3(NC/32, NC/32), tb>>>(wv_w, (__half*)wv, NC, NC);
    convT_kernel<<<dim3(FFDIM/32, NC/32), tb>>>(ff1_w, (__half*)f1, NC, FFDIM);
    convT_kernel<<<dim3(NC/32, FFDIM/32), tb>>>(ff2_w, (__half*)f2, FFDIM, NC);

    // QKV projections
    dim3 gQKV(NC / 128, NROWS / 128);
    tc_gemm<0><<<gQKV, 256, GEMM_SMEM>>>((__half*)pqh,  (__half*)wq, wq_b, (__half*)pQ, NC, NC);
    tc_gemm<0><<<gQKV, 256, GEMM_SMEM>>>((__half*)pkvh, (__half*)wk, wk_b, (__half*)pK, NC, NC);
    tc_gemm<0><<<gQKV, 256, GEMM_SMEM>>>((__half*)pkvh, (__half*)wv, wv_b, (__half*)pV, NC, NC);

    // attention middle
    colmax_part_kernel<<<BATCH * (NSEQ / 256), 256>>>();
    colmax_red_kernel<<<BATCH, 256>>>();
    ctx_part_kernel<<<dim3(NSPLIT, BATCH * NHEADS), 256>>>();
    ctx_reduce_kernel<<<BATCH * NHEADS, DH * DH>>>();
    attn_ln1_kernel<<<NROWS / ROWS_PER_BLK, 256>>>(q, ln1_g, ln1_b);

    // FF
    dim3 gFF1(FFDIM / 128, NROWS / 128);
    tc_gemm<1><<<gFF1, 256, GEMM_SMEM>>>((__half*)pxh, (__half*)f1, ff1_b, (__half*)phh, FFDIM, NC);
    dim3 gFF2(NC / 128, NROWS / 128);
    tc_gemm<0><<<gFF2, 256, GEMM_SMEM>>>((__half*)phh, (__half*)f2, ff2_b, (__half*)pF, NC, FFDIM);

    ln2_kernel<<<NROWS, 256>>>(ln2_g, ln2_b, out);
}

// round 8
// speedup vs baseline: 3.4695x; 1.0185x over previous
#include <cuda_runtime.h>
#include <cuda_fp16.h>
#include <math.h>
#include <stdint.h>

// Problem constants
#define BATCH   2
#define NSEQ    32768          // H*W*D
#define NC      256
#define NHEADS  8
#define DH      32
#define NROWS   (BATCH*NSEQ)   // 65536
#define FFDIM   1024
#define LN_EPS  1e-3f
#define NSPLIT  32

// ---------------- scratch (static __device__, no allocation) ----------------
__device__ __half g_Qp[(size_t)NROWS * NC];
__device__ __half g_Kp[(size_t)NROWS * NC];
__device__ __half g_Vp[(size_t)NROWS * NC];
__device__ float  g_x [(size_t)NROWS * NC];
__device__ __half g_ffout[(size_t)NROWS * NC];
__device__ float  g_partmax[(BATCH * (NSEQ/256)) * NC];
__device__ float  g_colmax[BATCH * NC];
__device__ float  g_Spart[(size_t)BATCH * NHEADS * NSPLIT * DH * DH];
__device__ float  g_Zpart[(size_t)BATCH * NHEADS * NSPLIT * DH];
__device__ float  g_ctx[BATCH * NHEADS * DH * DH];

__device__ __half g_qh [(size_t)NROWS * NC];
__device__ __half g_kvh[(size_t)NROWS * NC];
__device__ __half g_xh [(size_t)NROWS * NC];
__device__ __half g_hh [(size_t)NROWS * FFDIM];
__device__ __half g_wqT[NC*NC];
__device__ __half g_wkT[NC*NC];
__device__ __half g_wvT[NC*NC];
__device__ __half g_f1T[FFDIM*NC];
__device__ __half g_f2T[NC*FFDIM];

// ======================= PTX helpers =======================================
__device__ __forceinline__ uint32_t smem_u32(const void* p) {
    uint32_t a;
    asm("{ .reg .u64 t; cvta.to.shared.u64 t, %1; cvt.u32.u64 %0, t; }" : "=r"(a) : "l"(p));
    return a;
}
__device__ __forceinline__ void ldsm4(uint32_t* r, uint32_t addr) {
    asm volatile("ldmatrix.sync.aligned.m8n8.x4.shared.b16 {%0,%1,%2,%3}, [%4];"
        : "=r"(r[0]), "=r"(r[1]), "=r"(r[2]), "=r"(r[3]) : "r"(addr));
}
__device__ __forceinline__ void mma16816(float* c, const uint32_t* a, const uint32_t* b) {
    asm volatile("mma.sync.aligned.m16n8k16.row.col.f32.f16.f16.f32 "
        "{%0,%1,%2,%3}, {%4,%5,%6,%7}, {%8,%9}, {%0,%1,%2,%3};"
        : "+f"(c[0]), "+f"(c[1]), "+f"(c[2]), "+f"(c[3])
        : "r"(a[0]), "r"(a[1]), "r"(a[2]), "r"(a[3]), "r"(b[0]), "r"(b[1]));
}
#define CP16(dst, src) \
    asm volatile("cp.async.cg.shared.global [%0], [%1], 16;" :: "r"(dst), "l"(src))
#define CP_COMMIT()  asm volatile("cp.async.commit_group;" ::: "memory")
#define CP_WAIT1()   asm volatile("cp.async.wait_group 1;" ::: "memory")
#define CP_WAIT0()   asm volatile("cp.async.wait_group 0;" ::: "memory")

__device__ __forceinline__ float gelu_exact(float v) {
    return 0.5f * v * (1.0f + erff(v * 0.70710678118654752440f));
}

// ======================= HMMA fp16 GEMM =====================================
// C[M,N] = A[M,K] @ W[K,N]; A fp16 [M][K]; W fp16 [N][K].
// CTA tile 128x128, 4 warps (2x2, warp tile 64x64), k-chunk 64,
// 3-stage cp.async pipeline (single barrier / iter), 2 CTAs/SM.
#define KCH   64
#define BSTR  72
#define BSTRB (BSTR*2)                 // 144 bytes
#define TILEB (128*BSTRB)              // 18432 bytes per tile
#define NSTAGE 3
#define SOFF(s, t) (((s)*2 + (t)) * TILEB)
#define GEMM_SMEM (NSTAGE * 2 * TILEB) // 110592

// 128 threads load 128 rows x 64 halves
__device__ __forceinline__ void load_tile(const __half* __restrict__ src,
                                          uint32_t dstbase, int row0, int col0,
                                          int ldk, int tid) {
    const __half* s = src + (size_t)(row0 + (tid >> 3)) * ldk + col0 + (tid & 7) * 8;
    uint32_t d = dstbase + (uint32_t)(tid >> 3) * BSTRB + (uint32_t)(tid & 7) * 16;
    #pragma unroll
    for (int p = 0; p < 8; p++)
        CP16(d + p * 16 * BSTRB, s + (size_t)p * 16 * ldk);
}

template<int EPI>  // 0: bias -> fp16.  1: bias + gelu -> fp16.
__global__ __launch_bounds__(128, 2)
void tc_gemm(const __half* __restrict__ A, const __half* __restrict__ B,
             const float* __restrict__ bias, __half* __restrict__ C,
             int N, int K) {
    extern __shared__ __align__(1024) char smem[];
    const uint32_t sb = smem_u32(smem);
    const int tid  = threadIdx.x;
    const int wid  = tid >> 5;
    const int lane = tid & 31;
    const int wm = wid & 1;            // 2 row groups of 64
    const int wn = wid >> 1;           // 2 col groups of 64
    const int rowA0 = blockIdx.y * 128;
    const int rowB0 = blockIdx.x * 128;
    const int nch = K / KCH;

    const int row_a  = (lane & 7) + ((lane >> 3) & 1) * 8;
    const int kcol_a = (lane >> 4) * 8;
    const uint32_t aoff = (uint32_t)(wm * 64 + row_a) * BSTRB + kcol_a * 2;
    const int row_b  = (lane & 7) + (lane >> 4) * 8;
    const int kcol_b = ((lane >> 3) & 1) * 8;
    const uint32_t boff = (uint32_t)(wn * 64 + row_b) * BSTRB + kcol_b * 2;

    float c[4][8][4];
    #pragma unroll
    for (int i = 0; i < 4; i++)
        #pragma unroll
        for (int j = 0; j < 8; j++)
            #pragma unroll
            for (int q = 0; q < 4; q++) c[i][j][q] = 0.0f;

    // prologue: stages 0,1
    load_tile(A, sb + SOFF(0, 0), rowA0, 0, K, tid);
    load_tile(B, sb + SOFF(0, 1), rowB0, 0, K, tid);
    CP_COMMIT();
    if (nch > 1) {
        load_tile(A, sb + SOFF(1, 0), rowA0, KCH, K, tid);
        load_tile(B, sb + SOFF(1, 1), rowB0, KCH, K, tid);
        CP_COMMIT();
    }

    for (int ch = 0; ch < nch; ch++) {
        const int s = ch % NSTAGE;
        if (ch + 1 < nch) CP_WAIT1(); else CP_WAIT0();
        __syncthreads();
        if (ch + 2 < nch) {
            const int ns = (ch + 2) % NSTAGE;
            const int col0 = (ch + 2) * KCH;
            load_tile(A, sb + SOFF(ns, 0), rowA0, col0, K, tid);
            load_tile(B, sb + SOFF(ns, 1), rowB0, col0, K, tid);
            CP_COMMIT();
        }

        const uint32_t aP = sb + SOFF(s, 0) + aoff;
        const uint32_t bP = sb + SOFF(s, 1) + boff;

        #pragma unroll
        for (int ks = 0; ks < KCH / 16; ks++) {
            uint32_t a[4][4], b[8][2];
            #pragma unroll
            for (int mt = 0; mt < 4; mt++)
                ldsm4(a[mt], aP + mt * 16 * BSTRB + ks * 32);
            #pragma unroll
            for (int nt2 = 0; nt2 < 4; nt2++) {
                uint32_t r[4];
                ldsm4(r, bP + nt2 * 16 * BSTRB + ks * 32);
                b[nt2 * 2 + 0][0] = r[0]; b[nt2 * 2 + 0][1] = r[1];
                b[nt2 * 2 + 1][0] = r[2]; b[nt2 * 2 + 1][1] = r[3];
            }
            #pragma unroll
            for (int mt = 0; mt < 4; mt++)
                #pragma unroll
                for (int nt = 0; nt < 8; nt++)
                    mma16816(c[mt][nt], a[mt], b[nt]);
        }
    }

    // ---- epilogue: bias (+gelu) -> fp16 ----
    const int mrow = blockIdx.y * 128 + wm * 64 + (lane >> 2);
    const int ncol = blockIdx.x * 128 + wn * 64 + 2 * (lane & 3);
    #pragma unroll
    for (int mt = 0; mt < 4; mt++) {
        #pragma unroll
        for (int nt = 0; nt < 8; nt++) {
            const int col = ncol + nt * 8;
            const float b0 = bias[col], b1 = bias[col + 1];
            #pragma unroll
            for (int half_ = 0; half_ < 2; half_++) {
                const int row = mrow + mt * 16 + half_ * 8;
                float v0 = c[mt][nt][half_ * 2 + 0] + b0;
                float v1 = c[mt][nt][half_ * 2 + 1] + b1;
                if (EPI == 1) { v0 = gelu_exact(v0); v1 = gelu_exact(v1); }
                *(__half2*)(C + (size_t)row * N + col) = __floats2half2_rn(v0, v1);
            }
        }
    }
}

// ======================= conversion kernels =================================
// one launch converts both q and kv to fp16
__global__ void conv_half2_kernel(const float* __restrict__ x0, __half* __restrict__ d0,
                                  const float* __restrict__ x1, __half* __restrict__ d1) {
    const size_t half_grid = (size_t)NROWS * NC / 4 / 2;   // elements of 4 per tensor half? no:
    size_t gi = (size_t)blockIdx.x * blockDim.x + threadIdx.x;
    const float* x; __half* d;
    size_t n4 = (size_t)NROWS * NC / 4;
    if (gi < n4) { x = x0; d = d0; }
    else { x = x1; d = d1; gi -= n4; }
    size_t i = gi * 4;
    float4 v = *(const float4*)(x + i);
    __half2 a = __floats2half2_rn(v.x, v.y);
    __half2 b = __floats2half2_rn(v.z, v.w);
    *(uint2*)(d + i) = make_uint2(*(uint32_t*)&a, *(uint32_t*)&b);
    (void)half_grid;
}

// all 5 weight transposes in one launch: W[K][N] fp32 -> WT[N][K] fp16
__global__ void convT_all_kernel(const float* wq, const float* wk, const float* wv,
                                 const float* f1, const float* f2,
                                 __half* tq, __half* tk, __half* tv,
                                 __half* t1, __half* t2) {
    __shared__ float t[32][33];
    int b = blockIdx.x;
    const float* W; __half* T; int K, N;
    if      (b < 64)  { W = wq; T = tq; K = NC;    N = NC;    }
    else if (b < 128) { W = wk; T = tk; K = NC;    N = NC;    b -= 64;  }
    else if (b < 192) { W = wv; T = tv; K = NC;    N = NC;    b -= 128; }
    else if (b < 448) { W = f1; T = t1; K = NC;    N = FFDIM; b -= 192; }
    else              { W = f2; T = t2; K = FFDIM; N = NC;    b -= 448; }
    const int nx = N / 32;
    const int n0 = (b % nx) * 32, k0 = (b / nx) * 32;
    const int tx = threadIdx.x, ty = threadIdx.y;
    for (int i = ty; i < 32; i += 8) t[i][tx] = W[(size_t)(k0 + i) * N + n0 + tx];
    __syncthreads();
    for (int i = ty; i < 32; i += 8)
        T[(size_t)(n0 + i) * K + k0 + tx] = __float2half_rn(t[tx][i]);
}

// ======================= attention middle ===================================
__global__ void colmax_part_kernel() {
    const int chunk = blockIdx.x;
    const int b = chunk / (NSEQ / 256);
    const int r0 = (chunk % (NSEQ / 256)) * 256;
    const int c = threadIdx.x;
    const __half* base = g_Kp + ((size_t)b * NSEQ + r0) * NC;
    float m = -INFINITY;
    for (int r = 0; r < 256; r++)
        m = fmaxf(m, __half2float(base[(size_t)r * NC + c]));
    g_partmax[(size_t)chunk * NC + c] = m;
}
__global__ void colmax_red_kernel() {
    const int b = blockIdx.x;
    const int c = threadIdx.x;
    float m = -INFINITY;
    for (int ch = 0; ch < NSEQ / 256; ch++)
        m = fmaxf(m, g_partmax[((size_t)(b * (NSEQ / 256) + ch)) * NC + c]);
    g_colmax[b * NC + c] = m;
}
__global__ __launch_bounds__(256)
void ctx_part_kernel() {
    const int s  = blockIdx.x;
    const int bh = blockIdx.y;
    const int b = bh / NHEADS;
    const int h = bh % NHEADS;
    const int t = threadIdx.x;
    const int chunk = NSEQ / NSPLIT;
    __shared__ float ek[8][DH];
    __shared__ float vv[8][DH];
    const int e  = t & 31;
    const int d0 = (t >> 5) * 4;
    float acc0 = 0.f, acc1 = 0.f, acc2 = 0.f, acc3 = 0.f, zacc = 0.f;
    for (int g = 0; g < chunk / 8; g++) {
        #pragma unroll
        for (int i = 0; i < 2; i++) {
            int idx = t + i * 256;
            int row = idx >> 6;
            int col = idx & 63;
            int n = s * chunk + g * 8 + row;
            size_t base = ((size_t)b * NSEQ + n) * NC + h * DH;
            if (col < DH) {
                float kv = __half2float(g_Kp[base + col]);
                ek[row][col] = expf(kv - g_colmax[b * NC + h * DH + col]);
            } else {
                vv[row][col - DH] = __half2float(g_Vp[base + (col - DH)]);
            }
        }
        __syncthreads();
        #pragma unroll
        for (int row = 0; row < 8; row++) {
            float v = vv[row][e];
            acc0 = fmaf(ek[row][d0 + 0], v, acc0);
            acc1 = fmaf(ek[row][d0 + 1], v, acc1);
            acc2 = fmaf(ek[row][d0 + 2], v, acc2);
            acc3 = fmaf(ek[row][d0 + 3], v, acc3);
        }
        if (t < DH) {
            #pragma unroll
            for (int row = 0; row < 8; row++) zacc += ek[row][t];
        }
        __syncthreads();
    }
    const size_t sp = ((size_t)bh * NSPLIT + s) * (DH * DH);
    g_Spart[sp + (d0 + 0) * DH + e] = acc0;
    g_Spart[sp + (d0 + 1) * DH + e] = acc1;
    g_Spart[sp + (d0 + 2) * DH + e] = acc2;
    g_Spart[sp + (d0 + 3) * DH + e] = acc3;
    if (t < DH) g_Zpart[((size_t)bh * NSPLIT + s) * DH + t] = zacc;
}
__global__ void ctx_reduce_kernel() {
    const int bh = blockIdx.x;
    const int t = threadIdx.x;
    const int d = t >> 5;
    __shared__ float zs[DH];
    float ssum = 0.f;
    for (int p = 0; p < NSPLIT; p++)
        ssum += g_Spart[((size_t)bh * NSPLIT + p) * (DH * DH) + t];
    if (t < DH) {
        float z = 0.f;
        for (int p = 0; p < NSPLIT; p++)
            z += g_Zpart[((size_t)bh * NSPLIT + p) * DH + t];
        zs[t] = z;
    }
    __syncthreads();
    g_ctx[(size_t)bh * (DH * DH) + t] = ssum / zs[d];
}

// fused softmax(Q) -> attn -> +residual -> LN1
#define ROWS_PER_BLK 16
__global__ __launch_bounds__(256)
void attn_ln1_kernel(const float* __restrict__ qin,
                     const float* __restrict__ gamma,
                     const float* __restrict__ beta) {
    __shared__ float ctxs[NHEADS * DH * DH];
    __shared__ float r1[8], r2[8];
    const int t = threadIdx.x;
    const int row0 = blockIdx.x * ROWS_PER_BLK;
    const int b = row0 / NSEQ;
    for (int i = t; i < NHEADS * DH * DH; i += 256)
        ctxs[i] = g_ctx[(size_t)b * NHEADS * DH * DH + i];
    __syncthreads();
    const int h = t >> 5;
    const int lane = t & 31;
    const float gc = gamma[t];
    const float bc = beta[t];
    for (int r = 0; r < ROWS_PER_BLK; r++) {
        const size_t off = (size_t)(row0 + r) * NC;
        float qv = __half2float(g_Qp[off + t]);
        float m = qv;
        #pragma unroll
        for (int s = 16; s > 0; s >>= 1) m = fmaxf(m, __shfl_xor_sync(0xffffffffu, m, s));
        float ev = expf(qv - m);
        float ss = ev;
        #pragma unroll
        for (int s = 16; s > 0; s >>= 1) ss += __shfl_xor_sync(0xffffffffu, ss, s);
        float qn = ev / ss;
        float acc = 0.f;
        #pragma unroll
        for (int d = 0; d < DH; d++) {
            float qd = __shfl_sync(0xffffffffu, qn, d);
            acc = fmaf(qd, ctxs[h * (DH * DH) + d * DH + lane], acc);
        }
        float y = qin[off + t] + acc;
        float s1 = y, s2 = y * y;
        #pragma unroll
        for (int s = 16; s > 0; s >>= 1) {
            s1 += __shfl_xor_sync(0xffffffffu, s1, s);
            s2 += __shfl_xor_sync(0xffffffffu, s2, s);
        }
        if (lane == 0) { r1[h] = s1; r2[h] = s2; }
        __syncthreads();
        if (t == 0) {
            float a = 0.f, c2 = 0.f;
            #pragma unroll
            for (int i = 0; i < 8; i++) { a += r1[i]; c2 += r2[i]; }
            r1[0] = a; r2[0] = c2;
        }
        __syncthreads();
        float mean = r1[0] * (1.0f / NC);
        float var  = r2[0] * (1.0f / NC) - mean * mean;
        float xv = (y - mean) * rsqrtf(var + LN_EPS) * gc + bc;
        g_x[off + t] = xv;
        g_xh[off + t] = __float2half_rn(xv);
        __syncthreads();
    }
}

__global__ __launch_bounds__(256)
void ln2_kernel(const float* __restrict__ gamma, const float* __restrict__ beta,
                float* __restrict__ out) {
    __shared__ float r1[8], r2[8];
    const int t = threadIdx.x;
    const size_t off = (size_t)blockIdx.x * NC;
    const int h = t >> 5;
    const int lane = t & 31;
    float y = g_x[off + t] + __half2float(g_ffout[off + t]);
    float s1 = y, s2 = y * y;
    #pragma unroll
    for (int s = 16; s > 0; s >>= 1) {
        s1 += __shfl_xor_sync(0xffffffffu, s1, s);
        s2 += __shfl_xor_sync(0xffffffffu, s2, s);
    }
    if (lane == 0) { r1[h] = s1; r2[h] = s2; }
    __syncthreads();
    if (t == 0) {
        float a = 0.f, c2 = 0.f;
        #pragma unroll
        for (int i = 0; i < 8; i++) { a += r1[i]; c2 += r2[i]; }
        r1[0] = a; r2[0] = c2;
    }
    __syncthreads();
    float mean = r1[0] * (1.0f / NC);
    float var  = r2[0] * (1.0f / NC) - mean * mean;
    out[off + t] = (y - mean) * rsqrtf(var + LN_EPS) * gamma[t] + beta[t];
}

// ======================= launch =============================================
extern "C" void kernel_launch(void* const* d_in, const int* in_sizes, int n_in,
                              void* d_out, int out_size) {
    const float* q     = (const float*)d_in[0];
    const float* kv    = (const float*)d_in[1];
    const float* wq_w  = (const float*)d_in[2];
    const float* wq_b  = (const float*)d_in[3];
    const float* wk_w  = (const float*)d_in[4];
    const float* wk_b  = (const float*)d_in[5];
    const float* wv_w  = (const float*)d_in[6];
    const float* wv_b  = (const float*)d_in[7];
    const float* ln1_g = (const float*)d_in[8];
    const float* ln1_b = (const float*)d_in[9];
    const float* ff1_w = (const float*)d_in[10];
    const float* ff1_b = (const float*)d_in[11];
    const float* ff2_w = (const float*)d_in[12];
    const float* ff2_b = (const float*)d_in[13];
    const float* ln2_g = (const float*)d_in[14];
    const float* ln2_b = (const float*)d_in[15];
    float* out = (float*)d_out;

    void *pQ, *pK, *pV, *pF;
    void *pqh, *pkvh, *pxh, *phh;
    void *wq, *wk, *wv, *f1, *f2;
    cudaGetSymbolAddress(&pQ, g_Qp);    cudaGetSymbolAddress(&pK, g_Kp);
    cudaGetSymbolAddress(&pV, g_Vp);    cudaGetSymbolAddress(&pF, g_ffout);
    cudaGetSymbolAddress(&pqh, g_qh);   cudaGetSymbolAddress(&pkvh, g_kvh);
    cudaGetSymbolAddress(&pxh, g_xh);   cudaGetSymbolAddress(&phh, g_hh);
    cudaGetSymbolAddress(&wq, g_wqT);   cudaGetSymbolAddress(&wk, g_wkT);
    cudaGetSymbolAddress(&wv, g_wvT);   cudaGetSymbolAddress(&f1, g_f1T);
    cudaGetSymbolAddress(&f2, g_f2T);

    cudaFuncSetAttribute(tc_gemm<0>, cudaFuncAttributeMaxDynamicSharedMemorySize, GEMM_SMEM);
    cudaFuncSetAttribute(tc_gemm<1>, cudaFuncAttributeMaxDynamicSharedMemorySize, GEMM_SMEM);

    // input conversions (one launch for q+kv, one for all weights)
    const size_t n4 = (size_t)NROWS * NC / 4;
    conv_half2_kernel<<<(int)(2 * n4 / 256), 256>>>(q, (__half*)pqh, kv, (__half*)pkvh);
    dim3 tb(32, 8);
    convT_all_kernel<<<704, tb>>>(wq_w, wk_w, wv_w, ff1_w, ff2_w,
                                  (__half*)wq, (__half*)wk, (__half*)wv,
                                  (__half*)f1, (__half*)f2);

    // QKV projections
    dim3 gQKV(NC / 128, NROWS / 128);
    tc_gemm<0><<<gQKV, 128, GEMM_SMEM>>>((__half*)pqh,  (__half*)wq, wq_b, (__half*)pQ, NC, NC);
    tc_gemm<0><<<gQKV, 128, GEMM_SMEM>>>((__half*)pkvh, (__half*)wk, wk_b, (__half*)pK, NC, NC);
    tc_gemm<0><<<gQKV, 128, GEMM_SMEM>>>((__half*)pkvh, (__half*)wv, wv_b, (__half*)pV, NC, NC);

    // attention middle
    colmax_part_kernel<<<BATCH * (NSEQ / 256), 256>>>();
    colmax_red_kernel<<<BATCH, 256>>>();
    ctx_part_kernel<<<dim3(NSPLIT, BATCH * NHEADS), 256>>>();
    ctx_reduce_kernel<<<BATCH * NHEADS, DH * DH>>>();
    attn_ln1_kernel<<<NROWS / ROWS_PER_BLK, 256>>>(q, ln1_g, ln1_b);

    // FF
    dim3 gFF1(FFDIM / 128, NROWS / 128);
    tc_gemm<1><<<gFF1, 128, GEMM_SMEM>>>((__half*)pxh, (__half*)f1, ff1_b, (__half*)phh, FFDIM, NC);
    dim3 gFF2(NC / 128, NROWS / 128);
    tc_gemm<0><<<gFF2, 128, GEMM_SMEM>>>((__half*)phh, (__half*)f2, ff2_b, (__half*)pF, NC, FFDIM);

    ln2_kernel<<<NROWS, 256>>>(ln2_g, ln2_b, out);
}

// round 10
// speedup vs baseline: 3.4748x; 1.0015x over previous
#include <cuda_runtime.h>
#include <cuda_fp16.h>
#include <math.h>
#include <stdint.h>

// Problem constants
#define BATCH   2
#define NSEQ    32768          // H*W*D
#define NC      256
#define NHEADS  8
#define DH      32
#define NROWS   (BATCH*NSEQ)   // 65536
#define FFDIM   1024
#define LN_EPS  1e-3f
#define NSPLIT  32

// ---------------- scratch (static __device__, no allocation) ----------------
__device__ __half g_Qp[(size_t)NROWS * NC];
__device__ __half g_Kp[(size_t)NROWS * NC];
__device__ __half g_Vp[(size_t)NROWS * NC];
__device__ __half g_ffout[(size_t)NROWS * NC];
__device__ float  g_partmax[(BATCH * (NSEQ/256)) * NC];
__device__ float  g_colmax[BATCH * NC];
__device__ float  g_Spart[(size_t)BATCH * NHEADS * NSPLIT * DH * DH];
__device__ float  g_Zpart[(size_t)BATCH * NHEADS * NSPLIT * DH];
__device__ float  g_ctx[BATCH * NHEADS * DH * DH];

__device__ __half g_qh [(size_t)NROWS * NC];
__device__ __half g_kvh[(size_t)NROWS * NC];
__device__ __half g_xh [(size_t)NROWS * NC];
__device__ __half g_hh [(size_t)NROWS * FFDIM];
__device__ __half g_wqT [NC*NC];
__device__ __half g_wkvT[2*NC*NC];      // K rows [0,256), V rows [256,512)
__device__ __half g_f1T[FFDIM*NC];
__device__ __half g_f2T[NC*FFDIM];

// ======================= PTX helpers =======================================
__device__ __forceinline__ uint32_t smem_u32(const void* p) {
    uint32_t a;
    asm("{ .reg .u64 t; cvta.to.shared.u64 t, %1; cvt.u32.u64 %0, t; }" : "=r"(a) : "l"(p));
    return a;
}
__device__ __forceinline__ void ldsm4(uint32_t* r, uint32_t addr) {
    asm volatile("ldmatrix.sync.aligned.m8n8.x4.shared.b16 {%0,%1,%2,%3}, [%4];"
        : "=r"(r[0]), "=r"(r[1]), "=r"(r[2]), "=r"(r[3]) : "r"(addr));
}
__device__ __forceinline__ void mma16816(float* c, const uint32_t* a, const uint32_t* b) {
    asm volatile("mma.sync.aligned.m16n8k16.row.col.f32.f16.f16.f32 "
        "{%0,%1,%2,%3}, {%4,%5,%6,%7}, {%8,%9}, {%0,%1,%2,%3};"
        : "+f"(c[0]), "+f"(c[1]), "+f"(c[2]), "+f"(c[3])
        : "r"(a[0]), "r"(a[1]), "r"(a[2]), "r"(a[3]), "r"(b[0]), "r"(b[1]));
}
#define CP16(dst, src) \
    asm volatile("cp.async.cg.shared.global [%0], [%1], 16;" :: "r"(dst), "l"(src))
#define CP_COMMIT()  asm volatile("cp.async.commit_group;" ::: "memory")
#define CP_WAIT1()   asm volatile("cp.async.wait_group 1;" ::: "memory")
#define CP_WAIT0()   asm volatile("cp.async.wait_group 0;" ::: "memory")

__device__ __forceinline__ float gelu_exact(float v) {
    return 0.5f * v * (1.0f + erff(v * 0.70710678118654752440f));
}

// ======================= HMMA fp16 GEMM =====================================
// C[M,N] = A[M,K] @ W[K,N]; A fp16 [M][K]; W fp16 [N][K].
// CTA tile 128x128, 4 warps (2x2, warp tile 64x64), k-chunk 64,
// 3-stage cp.async pipeline, smem-staged coalesced epilogue, 2 CTAs/SM.
#define KCH   64
#define BSTR  72
#define BSTRB (BSTR*2)                 // 144 bytes
#define TILEB (128*BSTRB)              // 18432 bytes per tile
#define NSTAGE 3
#define SOFF(s, t) (((s)*2 + (t)) * TILEB)
#define GEMM_SMEM (NSTAGE * 2 * TILEB) // 110592

__device__ __forceinline__ void load_tile(const __half* __restrict__ src,
                                          uint32_t dstbase, int row0, int col0,
                                          int ldk, int tid) {
    const __half* s = src + (size_t)(row0 + (tid >> 3)) * ldk + col0 + (tid & 7) * 8;
    uint32_t d = dstbase + (uint32_t)(tid >> 3) * BSTRB + (uint32_t)(tid & 7) * 16;
    #pragma unroll
    for (int p = 0; p < 8; p++)
        CP16(d + p * 16 * BSTRB, s + (size_t)p * 16 * ldk);
}

// EPI 0: bias.  EPI 1: bias + gelu.  FUSE: N=512, cols<256 -> C / else -> C2.
template<int EPI, int FUSE>
__global__ __launch_bounds__(128, 2)
void tc_gemm(const __half* __restrict__ A, const __half* __restrict__ B,
             const float* __restrict__ bias, const float* __restrict__ bias2,
             __half* __restrict__ C, __half* __restrict__ C2,
             int N, int K) {
    extern __shared__ __align__(1024) char smem[];
    const uint32_t sb = smem_u32(smem);
    const int tid  = threadIdx.x;
    const int wid  = tid >> 5;
    const int lane = tid & 31;
    const int wm = wid & 1;            // 2 row groups of 64
    const int wn = wid >> 1;           // 2 col groups of 64
    const int rowA0 = blockIdx.y * 128;
    const int rowB0 = blockIdx.x * 128;
    const int nch = K / KCH;

    // output routing
    __half* Cout; const float* bi; int colbase, ldC;
    if (FUSE) {
        int gc = blockIdx.x * 128;
        if (gc < 256) { Cout = C;  bi = bias;  colbase = gc; }
        else          { Cout = C2; bi = bias2; colbase = gc - 256; }
        ldC = 256;
    } else {
        Cout = C; bi = bias; colbase = blockIdx.x * 128; ldC = N;
    }

    const int row_a  = (lane & 7) + ((lane >> 3) & 1) * 8;
    const int kcol_a = (lane >> 4) * 8;
    const uint32_t aoff = (uint32_t)(wm * 64 + row_a) * BSTRB + kcol_a * 2;
    const int row_b  = (lane & 7) + (lane >> 4) * 8;
    const int kcol_b = ((lane >> 3) & 1) * 8;
    const uint32_t boff = (uint32_t)(wn * 64 + row_b) * BSTRB + kcol_b * 2;

    float c[4][8][4];
    #pragma unroll
    for (int i = 0; i < 4; i++)
        #pragma unroll
        for (int j = 0; j < 8; j++)
            #pragma unroll
            for (int q = 0; q < 4; q++) c[i][j][q] = 0.0f;

    load_tile(A, sb + SOFF(0, 0), rowA0, 0, K, tid);
    load_tile(B, sb + SOFF(0, 1), rowB0, 0, K, tid);
    CP_COMMIT();
    if (nch > 1) {
        load_tile(A, sb + SOFF(1, 0), rowA0, KCH, K, tid);
        load_tile(B, sb + SOFF(1, 1), rowB0, KCH, K, tid);
        CP_COMMIT();
    }

    for (int ch = 0; ch < nch; ch++) {
        const int s = ch % NSTAGE;
        if (ch + 1 < nch) CP_WAIT1(); else CP_WAIT0();
        __syncthreads();
        if (ch + 2 < nch) {
            const int ns = (ch + 2) % NSTAGE;
            const int col0 = (ch + 2) * KCH;
            load_tile(A, sb + SOFF(ns, 0), rowA0, col0, K, tid);
            load_tile(B, sb + SOFF(ns, 1), rowB0, col0, K, tid);
            CP_COMMIT();
        }

        const uint32_t aP = sb + SOFF(s, 0) + aoff;
        const uint32_t bP = sb + SOFF(s, 1) + boff;

        #pragma unroll
        for (int ks = 0; ks < KCH / 16; ks++) {
            uint32_t a[4][4], b[8][2];
            #pragma unroll
            for (int mt = 0; mt < 4; mt++)
                ldsm4(a[mt], aP + mt * 16 * BSTRB + ks * 32);
            #pragma unroll
            for (int nt2 = 0; nt2 < 4; nt2++) {
                uint32_t r[4];
                ldsm4(r, bP + nt2 * 16 * BSTRB + ks * 32);
                b[nt2 * 2 + 0][0] = r[0]; b[nt2 * 2 + 0][1] = r[1];
                b[nt2 * 2 + 1][0] = r[2]; b[nt2 * 2 + 1][1] = r[3];
            }
            #pragma unroll
            for (int mt = 0; mt < 4; mt++)
                #pragma unroll
                for (int nt = 0; nt < 8; nt++)
                    mma16816(c[mt][nt], a[mt], b[nt]);
        }
    }

    // ---- epilogue: bias (+gelu) -> half2 -> swizzled smem stage -> 128B rows
    __syncthreads();                       // all warps done with tile smem
    char* wst = smem + wid * 8192;         // warp-private 64x128B staging
    #pragma unroll
    for (int mt = 0; mt < 4; mt++) {
        #pragma unroll
        for (int nt = 0; nt < 8; nt++) {
            const int colw = nt * 8 + 2 * (lane & 3);           // 0..62
            const int colg = colbase + wn * 64 + colw;
            const float b0 = bi[colg], b1 = bi[colg + 1];
            #pragma unroll
            for (int h = 0; h < 2; h++) {
                const int rloc = mt * 16 + h * 8 + (lane >> 2); // 0..63
                float v0 = c[mt][nt][h * 2 + 0] + b0;
                float v1 = c[mt][nt][h * 2 + 1] + b1;
                if (EPI == 1) { v0 = gelu_exact(v0); v1 = gelu_exact(v1); }
                __half2 p = __floats2half2_rn(v0, v1);
                uint32_t off = (uint32_t)rloc * 128 + colw * 2;
                off ^= ((off >> 3) & 0x70);
                *(uint32_t*)(wst + off) = *(uint32_t*)&p;
            }
        }
    }
    __syncwarp();
    const int rowg0 = blockIdx.y * 128 + wm * 64;
    const int colg0 = colbase + wn * 64;
    #pragma unroll
    for (int p = 0; p < 16; p++) {
        const int rloc = p * 4 + (lane >> 3);       // 0..63
        const int ch8  = lane & 7;                  // 16B chunk
        uint32_t off = (uint32_t)rloc * 128 + (uint32_t)((ch8 ^ (rloc & 7)) * 16);
        uint4 val = *(uint4*)(wst + off);
        *(uint4*)(Cout + (size_t)(rowg0 + rloc) * ldC + colg0 + ch8 * 8) = val;
    }
}

// ======================= conversion kernels =================================
__global__ void conv_half2_kernel(const float* __restrict__ x0, __half* __restrict__ d0,
                                  const float* __restrict__ x1, __half* __restrict__ d1) {
    size_t gi = (size_t)blockIdx.x * blockDim.x + threadIdx.x;
    const float* x; __half* d;
    size_t n4 = (size_t)NROWS * NC / 4;
    if (gi < n4) { x = x0; d = d0; }
    else { x = x1; d = d1; gi -= n4; }
    size_t i = gi * 4;
    float4 v = *(const float4*)(x + i);
    __half2 a = __floats2half2_rn(v.x, v.y);
    __half2 b = __floats2half2_rn(v.z, v.w);
    *(uint2*)(d + i) = make_uint2(*(uint32_t*)&a, *(uint32_t*)&b);
}

// all 5 weight transposes in one launch: W[K][N] fp32 -> WT[N][K] fp16
__global__ void convT_all_kernel(const float* wq, const float* wk, const float* wv,
                                 const float* f1, const float* f2,
                                 __half* tq, __half* tk, __half* tv,
                                 __half* t1, __half* t2) {
    __shared__ float t[32][33];
    int b = blockIdx.x;
    const float* W; __half* T; int K, N;
    if      (b < 64)  { W = wq; T = tq; K = NC;    N = NC;    }
    else if (b < 128) { W = wk; T = tk; K = NC;    N = NC;    b -= 64;  }
    else if (b < 192) { W = wv; T = tv; K = NC;    N = NC;    b -= 128; }
    else if (b < 448) { W = f1; T = t1; K = NC;    N = FFDIM; b -= 192; }
    else              { W = f2; T = t2; K = FFDIM; N = NC;    b -= 448; }
    const int nx = N / 32;
    const int n0 = (b % nx) * 32, k0 = (b / nx) * 32;
    const int tx = threadIdx.x, ty = threadIdx.y;
    for (int i = ty; i < 32; i += 8) t[i][tx] = W[(size_t)(k0 + i) * N + n0 + tx];
    __syncthreads();
    for (int i = ty; i < 32; i += 8)
        T[(size_t)(n0 + i) * K + k0 + tx] = __float2half_rn(t[tx][i]);
}

// ======================= attention middle ===================================
__global__ void colmax_part_kernel() {
    const int chunk = blockIdx.x;
    const int b = chunk / (NSEQ / 256);
    const int r0 = (chunk % (NSEQ / 256)) * 256;
    const int c = threadIdx.x;
    const __half* base = g_Kp + ((size_t)b * NSEQ + r0) * NC;
    float m = -INFINITY;
    for (int r = 0; r < 256; r++)
        m = fmaxf(m, __half2float(base[(size_t)r * NC + c]));
    g_partmax[(size_t)chunk * NC + c] = m;
}
__global__ void colmax_red_kernel() {
    const int b = blockIdx.x;
    const int c = threadIdx.x;
    float m = -INFINITY;
    for (int ch = 0; ch < NSEQ / 256; ch++)
        m = fmaxf(m, g_partmax[((size_t)(b * (NSEQ / 256) + ch)) * NC + c]);
    g_colmax[b * NC + c] = m;
}
__global__ __launch_bounds__(256)
void ctx_part_kernel() {
    const int s  = blockIdx.x;
    const int bh = blockIdx.y;
    const int b = bh / NHEADS;
    const int h = bh % NHEADS;
    const int t = threadIdx.x;
    const int chunk = NSEQ / NSPLIT;
    __shared__ float ek[8][DH];
    __shared__ float vv[8][DH];
    const int e  = t & 31;
    const int d0 = (t >> 5) * 4;
    float acc0 = 0.f, acc1 = 0.f, acc2 = 0.f, acc3 = 0.f, zacc = 0.f;
    for (int g = 0; g < chunk / 8; g++) {
        #pragma unroll
        for (int i = 0; i < 2; i++) {
            int idx = t + i * 256;
            int row = idx >> 6;
            int col = idx & 63;
            int n = s * chunk + g * 8 + row;
            size_t base = ((size_t)b * NSEQ + n) * NC + h * DH;
            if (col < DH) {
                float kv = __half2float(g_Kp[base + col]);
                ek[row][col] = expf(kv - g_colmax[b * NC + h * DH + col]);
            } else {
                vv[row][col - DH] = __half2float(g_Vp[base + (col - DH)]);
            }
        }
        __syncthreads();
        #pragma unroll
        for (int row = 0; row < 8; row++) {
            float v = vv[row][e];
            acc0 = fmaf(ek[row][d0 + 0], v, acc0);
            acc1 = fmaf(ek[row][d0 + 1], v, acc1);
            acc2 = fmaf(ek[row][d0 + 2], v, acc2);
            acc3 = fmaf(ek[row][d0 + 3], v, acc3);
        }
        if (t < DH) {
            #pragma unroll
            for (int row = 0; row < 8; row++) zacc += ek[row][t];
        }
        __syncthreads();
    }
    const size_t sp = ((size_t)bh * NSPLIT + s) * (DH * DH);
    g_Spart[sp + (d0 + 0) * DH + e] = acc0;
    g_Spart[sp + (d0 + 1) * DH + e] = acc1;
    g_Spart[sp + (d0 + 2) * DH + e] = acc2;
    g_Spart[sp + (d0 + 3) * DH + e] = acc3;
    if (t < DH) g_Zpart[((size_t)bh * NSPLIT + s) * DH + t] = zacc;
}
__global__ void ctx_reduce_kernel() {
    const int bh = blockIdx.x;
    const int t = threadIdx.x;
    const int d = t >> 5;
    __shared__ float zs[DH];
    float ssum = 0.f;
    for (int p = 0; p < NSPLIT; p++)
        ssum += g_Spart[((size_t)bh * NSPLIT + p) * (DH * DH) + t];
    if (t < DH) {
        float z = 0.f;
        for (int p = 0; p < NSPLIT; p++)
            z += g_Zpart[((size_t)bh * NSPLIT + p) * DH + t];
        zs[t] = z;
    }
    __syncthreads();
    g_ctx[(size_t)bh * (DH * DH) + t] = ssum / zs[d];
}

// fused softmax(Q) -> attn -> +residual -> LN1 (emits fp16 x only)
#define ROWS_PER_BLK 16
__global__ __launch_bounds__(256)
void attn_ln1_kernel(const float* __restrict__ qin,
                     const float* __restrict__ gamma,
                     const float* __restrict__ beta) {
    __shared__ float ctxs[NHEADS * DH * DH];
    __shared__ float r1[8], r2[8];
    const int t = threadIdx.x;
    const int row0 = blockIdx.x * ROWS_PER_BLK;
    const int b = row0 / NSEQ;
    for (int i = t; i < NHEADS * DH * DH; i += 256)
        ctxs[i] = g_ctx[(size_t)b * NHEADS * DH * DH + i];
    __syncthreads();
    const int h = t >> 5;
    const int lane = t & 31;
    const float gc = gamma[t];
    const float bc = beta[t];
    for (int r = 0; r < ROWS_PER_BLK; r++) {
        const size_t off = (size_t)(row0 + r) * NC;
        float qv = __half2float(g_Qp[off + t]);
        float m = qv;
        #pragma unroll
        for (int s = 16; s > 0; s >>= 1) m = fmaxf(m, __shfl_xor_sync(0xffffffffu, m, s));
        float ev = expf(qv - m);
        float ss = ev;
        #pragma unroll
        for (int s = 16; s > 0; s >>= 1) ss += __shfl_xor_sync(0xffffffffu, ss, s);
        float qn = ev / ss;
        float acc = 0.f;
        #pragma unroll
        for (int d = 0; d < DH; d++) {
            float qd = __shfl_sync(0xffffffffu, qn, d);
            acc = fmaf(qd, ctxs[h * (DH * DH) + d * DH + lane], acc);
        }
        float y = qin[off + t] + acc;
        float s1 = y, s2 = y * y;
        #pragma unroll
        for (int s = 16; s > 0; s >>= 1) {
            s1 += __shfl_xor_sync(0xffffffffu, s1, s);
            s2 += __shfl_xor_sync(0xffffffffu, s2, s);
        }
        if (lane == 0) { r1[h] = s1; r2[h] = s2; }
        __syncthreads();
        if (t == 0) {
            float a = 0.f, c2 = 0.f;
            #pragma unroll
            for (int i = 0; i < 8; i++) { a += r1[i]; c2 += r2[i]; }
            r1[0] = a; r2[0] = c2;
        }
        __syncthreads();
        float mean = r1[0] * (1.0f / NC);
        float var  = r2[0] * (1.0f / NC) - mean * mean;
        float xv = (y - mean) * rsqrtf(var + LN_EPS) * gc + bc;
        g_xh[off + t] = __float2half_rn(xv);
        __syncthreads();
    }
}

__global__ __launch_bounds__(256)
void ln2_kernel(const float* __restrict__ gamma, const float* __restrict__ beta,
                float* __restrict__ out) {
    __shared__ float r1[8], r2[8];
    const int t = threadIdx.x;
    const size_t off = (size_t)blockIdx.x * NC;
    const int h = t >> 5;
    const int lane = t & 31;
    float y = __half2float(g_xh[off + t]) + __half2float(g_ffout[off + t]);
    float s1 = y, s2 = y * y;
    #pragma unroll
    for (int s = 16; s > 0; s >>= 1) {
        s1 += __shfl_xor_sync(0xffffffffu, s1, s);
        s2 += __shfl_xor_sync(0xffffffffu, s2, s);
    }
    if (lane == 0) { r1[h] = s1; r2[h] = s2; }
    __syncthreads();
    if (t == 0) {
        float a = 0.f, c2 = 0.f;
        #pragma unroll
        for (int i = 0; i < 8; i++) { a += r1[i]; c2 += r2[i]; }
        r1[0] = a; r2[0] = c2;
    }
    __syncthreads();
    float mean = r1[0] * (1.0f / NC);
    float var  = r2[0] * (1.0f / NC) - mean * mean;
    out[off + t] = (y - mean) * rsqrtf(var + LN_EPS) * gamma[t] + beta[t];
}

// ======================= launch =============================================
extern "C" void kernel_launch(void* const* d_in, const int* in_sizes, int n_in,
                              void* d_out, int out_size) {
    const float* q     = (const float*)d_in[0];
    const float* kv    = (const float*)d_in[1];
    const float* wq_w  = (const float*)d_in[2];
    const float* wq_b  = (const float*)d_in[3];
    const float* wk_w  = (const float*)d_in[4];
    const float* wk_b  = (const float*)d_in[5];
    const float* wv_w  = (const float*)d_in[6];
    const float* wv_b  = (const float*)d_in[7];
    const float* ln1_g = (const float*)d_in[8];
    const float* ln1_b = (const float*)d_in[9];
    const float* ff1_w = (const float*)d_in[10];
    const float* ff1_b = (const float*)d_in[11];
    const float* ff2_w = (const float*)d_in[12];
    const float* ff2_b = (const float*)d_in[13];
    const float* ln2_g = (const float*)d_in[14];
    const float* ln2_b = (const float*)d_in[15];
    float* out = (float*)d_out;

    void *pQ, *pK, *pV, *pF;
    void *pqh, *pkvh, *pxh, *phh;
    void *wq, *wkv, *f1, *f2;
    cudaGetSymbolAddress(&pQ, g_Qp);    cudaGetSymbolAddress(&pK, g_Kp);
    cudaGetSymbolAddress(&pV, g_Vp);    cudaGetSymbolAddress(&pF, g_ffout);
    cudaGetSymbolAddress(&pqh, g_qh);   cudaGetSymbolAddress(&pkvh, g_kvh);
    cudaGetSymbolAddress(&pxh, g_xh);   cudaGetSymbolAddress(&phh, g_hh);
    cudaGetSymbolAddress(&wq, g_wqT);   cudaGetSymbolAddress(&wkv, g_wkvT);
    cudaGetSymbolAddress(&f1, g_f1T);   cudaGetSymbolAddress(&f2, g_f2T);

    cudaFuncSetAttribute(tc_gemm<0,0>, cudaFuncAttributeMaxDynamicSharedMemorySize, GEMM_SMEM);
    cudaFuncSetAttribute(tc_gemm<0,1>, cudaFuncAttributeMaxDynamicSharedMemorySize, GEMM_SMEM);
    cudaFuncSetAttribute(tc_gemm<1,0>, cudaFuncAttributeMaxDynamicSharedMemorySize, GEMM_SMEM);

    // input conversions (one launch for q+kv, one for all weights)
    const size_t n4 = (size_t)NROWS * NC / 4;
    conv_half2_kernel<<<(int)(2 * n4 / 256), 256>>>(q, (__half*)pqh, kv, (__half*)pkvh);
    dim3 tb(32, 8);
    convT_all_kernel<<<704, tb>>>(wq_w, wk_w, wv_w, ff1_w, ff2_w,
                                  (__half*)wq, (__half*)wkv,
                                  (__half*)wkv + 256 * NC,
                                  (__half*)f1, (__half*)f2);

    // projections: Q alone; K+V fused (shared A)
    dim3 gQ(NC / 128, NROWS / 128);
    tc_gemm<0,0><<<gQ, 128, GEMM_SMEM>>>((__half*)pqh, (__half*)wq, wq_b, 0,
                                         (__half*)pQ, 0, NC, NC);
    dim3 gKV(512 / 128, NROWS / 128);
    tc_gemm<0,1><<<gKV, 128, GEMM_SMEM>>>((__half*)pkvh, (__half*)wkv, wk_b, wv_b,
                                          (__half*)pK, (__half*)pV, 512, NC);

    // attention middle
    colmax_part_kernel<<<BATCH * (NSEQ / 256), 256>>>();
    colmax_red_kernel<<<BATCH, 256>>>();
    ctx_part_kernel<<<dim3(NSPLIT, BATCH * NHEADS), 256>>>();
    ctx_reduce_kernel<<<BATCH * NHEADS, DH * DH>>>();
    attn_ln1_kernel<<<NROWS / ROWS_PER_BLK, 256>>>(q, ln1_g, ln1_b);

    // FF
    dim3 gFF1(FFDIM / 128, NROWS / 128);
    tc_gemm<1,0><<<gFF1, 128, GEMM_SMEM>>>((__half*)pxh, (__half*)f1, ff1_b, 0,
                                           (__half*)phh, 0, FFDIM, NC);
    dim3 gFF2(NC / 128, NROWS / 128);
    tc_gemm<0,0><<<gFF2, 128, GEMM_SMEM>>>((__half*)phh, (__half*)f2, ff2_b, 0,
                                           (__half*)pF, 0, NC, FFDIM);

    ln2_kernel<<<NROWS, 256>>>(ln2_g, ln2_b, out);
}

// round 11
// speedup vs baseline: 4.1283x; 1.1881x over previous
#include <cuda_runtime.h>
#include <cuda_fp16.h>
#include <math.h>
#include <stdint.h>

// Problem constants
#define BATCH   2
#define NSEQ    32768          // H*W*D
#define NC      256
#define NHEADS  8
#define DH      32
#define NROWS   (BATCH*NSEQ)   // 65536
#define FFDIM   1024
#define LN_EPS  1e-3f
#define NSPLIT  32

// ---------------- scratch (static __device__, no allocation) ----------------
__device__ __half g_Qp[(size_t)NROWS * NC];
__device__ __half g_Kp[(size_t)NROWS * NC];
__device__ __half g_Vp[(size_t)NROWS * NC];
__device__ __half g_ffout[(size_t)NROWS * NC];
__device__ float  g_partmax[(BATCH * (NSEQ/256)) * NC];
__device__ float  g_colmax[BATCH * NC];
__device__ float  g_Spart[(size_t)BATCH * NHEADS * NSPLIT * DH * DH];
__device__ float  g_Zpart[(size_t)BATCH * NHEADS * NSPLIT * DH];
__device__ float  g_ctx[BATCH * NHEADS * DH * DH];

__device__ __half g_qh [(size_t)NROWS * NC];
__device__ __half g_kvh[(size_t)NROWS * NC];
__device__ __half g_xh [(size_t)NROWS * NC];
__device__ __half g_hh [(size_t)NROWS * FFDIM];
__device__ __half g_wqT [NC*NC];
__device__ __half g_wkvT[2*NC*NC];      // K rows [0,256), V rows [256,512)
__device__ __half g_f1T[FFDIM*NC];
__device__ __half g_f2T[NC*FFDIM];

// ======================= PTX helpers =======================================
__device__ __forceinline__ uint32_t smem_u32(const void* p) {
    uint32_t a;
    asm("{ .reg .u64 t; cvta.to.shared.u64 t, %1; cvt.u32.u64 %0, t; }" : "=r"(a) : "l"(p));
    return a;
}
__device__ __forceinline__ void ldsm4(uint32_t* r, uint32_t addr) {
    asm volatile("ldmatrix.sync.aligned.m8n8.x4.shared.b16 {%0,%1,%2,%3}, [%4];"
        : "=r"(r[0]), "=r"(r[1]), "=r"(r[2]), "=r"(r[3]) : "r"(addr));
}
__device__ __forceinline__ void mma16816(float* c, const uint32_t* a, const uint32_t* b) {
    asm volatile("mma.sync.aligned.m16n8k16.row.col.f32.f16.f16.f32 "
        "{%0,%1,%2,%3}, {%4,%5,%6,%7}, {%8,%9}, {%0,%1,%2,%3};"
        : "+f"(c[0]), "+f"(c[1]), "+f"(c[2]), "+f"(c[3])
        : "r"(a[0]), "r"(a[1]), "r"(a[2]), "r"(a[3]), "r"(b[0]), "r"(b[1]));
}
#define CP16(dst, src) \
    asm volatile("cp.async.cg.shared.global [%0], [%1], 16;" :: "r"(dst), "l"(src))
#define CP_COMMIT()  asm volatile("cp.async.commit_group;" ::: "memory")
#define CP_WAIT1()   asm volatile("cp.async.wait_group 1;" ::: "memory")
#define CP_WAIT0()   asm volatile("cp.async.wait_group 0;" ::: "memory")

__device__ __forceinline__ float gelu_exact(float v) {
    return 0.5f * v * (1.0f + erff(v * 0.70710678118654752440f));
}

// ======================= HMMA fp16 GEMM (unchanged core) ====================
#define KCH   64
#define BSTR  72
#define BSTRB (BSTR*2)
#define TILEB (128*BSTRB)
#define NSTAGE 3
#define SOFF(s, t) (((s)*2 + (t)) * TILEB)
#define GEMM_SMEM (NSTAGE * 2 * TILEB) // 110592

__device__ __forceinline__ void load_tile(const __half* __restrict__ src,
                                          uint32_t dstbase, int row0, int col0,
                                          int ldk, int tid) {
    const __half* s = src + (size_t)(row0 + (tid >> 3)) * ldk + col0 + (tid & 7) * 8;
    uint32_t d = dstbase + (uint32_t)(tid >> 3) * BSTRB + (uint32_t)(tid & 7) * 16;
    #pragma unroll
    for (int p = 0; p < 8; p++)
        CP16(d + p * 16 * BSTRB, s + (size_t)p * 16 * ldk);
}

template<int EPI, int FUSE>
__global__ __launch_bounds__(128, 2)
void tc_gemm(const __half* __restrict__ A, const __half* __restrict__ B,
             const float* __restrict__ bias, const float* __restrict__ bias2,
             __half* __restrict__ C, __half* __restrict__ C2,
             int N, int K) {
    extern __shared__ __align__(1024) char smem[];
    const uint32_t sb = smem_u32(smem);
    const int tid  = threadIdx.x;
    const int wid  = tid >> 5;
    const int lane = tid & 31;
    const int wm = wid & 1;
    const int wn = wid >> 1;
    const int rowA0 = blockIdx.y * 128;
    const int rowB0 = blockIdx.x * 128;
    const int nch = K / KCH;

    __half* Cout; const float* bi; int colbase, ldC;
    if (FUSE) {
        int gc = blockIdx.x * 128;
        if (gc < 256) { Cout = C;  bi = bias;  colbase = gc; }
        else          { Cout = C2; bi = bias2; colbase = gc - 256; }
        ldC = 256;
    } else {
        Cout = C; bi = bias; colbase = blockIdx.x * 128; ldC = N;
    }

    const int row_a  = (lane & 7) + ((lane >> 3) & 1) * 8;
    const int kcol_a = (lane >> 4) * 8;
    const uint32_t aoff = (uint32_t)(wm * 64 + row_a) * BSTRB + kcol_a * 2;
    const int row_b  = (lane & 7) + (lane >> 4) * 8;
    const int kcol_b = ((lane >> 3) & 1) * 8;
    const uint32_t boff = (uint32_t)(wn * 64 + row_b) * BSTRB + kcol_b * 2;

    float c[4][8][4];
    #pragma unroll
    for (int i = 0; i < 4; i++)
        #pragma unroll
        for (int j = 0; j < 8; j++)
            #pragma unroll
            for (int q = 0; q < 4; q++) c[i][j][q] = 0.0f;

    load_tile(A, sb + SOFF(0, 0), rowA0, 0, K, tid);
    load_tile(B, sb + SOFF(0, 1), rowB0, 0, K, tid);
    CP_COMMIT();
    if (nch > 1) {
        load_tile(A, sb + SOFF(1, 0), rowA0, KCH, K, tid);
        load_tile(B, sb + SOFF(1, 1), rowB0, KCH, K, tid);
        CP_COMMIT();
    }

    for (int ch = 0; ch < nch; ch++) {
        const int s = ch % NSTAGE;
        if (ch + 1 < nch) CP_WAIT1(); else CP_WAIT0();
        __syncthreads();
        if (ch + 2 < nch) {
            const int ns = (ch + 2) % NSTAGE;
            const int col0 = (ch + 2) * KCH;
            load_tile(A, sb + SOFF(ns, 0), rowA0, col0, K, tid);
            load_tile(B, sb + SOFF(ns, 1), rowB0, col0, K, tid);
            CP_COMMIT();
        }

        const uint32_t aP = sb + SOFF(s, 0) + aoff;
        const uint32_t bP = sb + SOFF(s, 1) + boff;

        #pragma unroll
        for (int ks = 0; ks < KCH / 16; ks++) {
            uint32_t a[4][4], b[8][2];
            #pragma unroll
            for (int mt = 0; mt < 4; mt++)
                ldsm4(a[mt], aP + mt * 16 * BSTRB + ks * 32);
            #pragma unroll
            for (int nt2 = 0; nt2 < 4; nt2++) {
                uint32_t r[4];
                ldsm4(r, bP + nt2 * 16 * BSTRB + ks * 32);
                b[nt2 * 2 + 0][0] = r[0]; b[nt2 * 2 + 0][1] = r[1];
                b[nt2 * 2 + 1][0] = r[2]; b[nt2 * 2 + 1][1] = r[3];
            }
            #pragma unroll
            for (int mt = 0; mt < 4; mt++)
                #pragma unroll
                for (int nt = 0; nt < 8; nt++)
                    mma16816(c[mt][nt], a[mt], b[nt]);
        }
    }

    // epilogue: bias (+gelu) -> swizzled smem stage -> 128B coalesced rows
    __syncthreads();
    char* wst = smem + wid * 8192;
    #pragma unroll
    for (int mt = 0; mt < 4; mt++) {
        #pragma unroll
        for (int nt = 0; nt < 8; nt++) {
            const int colw = nt * 8 + 2 * (lane & 3);
            const int colg = colbase + wn * 64 + colw;
            const float b0 = bi[colg], b1 = bi[colg + 1];
            #pragma unroll
            for (int h = 0; h < 2; h++) {
                const int rloc = mt * 16 + h * 8 + (lane >> 2);
                float v0 = c[mt][nt][h * 2 + 0] + b0;
                float v1 = c[mt][nt][h * 2 + 1] + b1;
                if (EPI == 1) { v0 = gelu_exact(v0); v1 = gelu_exact(v1); }
                __half2 p = __floats2half2_rn(v0, v1);
                uint32_t off = (uint32_t)rloc * 128 + colw * 2;
                off ^= ((off >> 3) & 0x70);
                *(uint32_t*)(wst + off) = *(uint32_t*)&p;
            }
        }
    }
    __syncwarp();
    const int rowg0 = blockIdx.y * 128 + wm * 64;
    const int colg0 = colbase + wn * 64;
    #pragma unroll
    for (int p = 0; p < 16; p++) {
        const int rloc = p * 4 + (lane >> 3);
        const int ch8  = lane & 7;
        uint32_t off = (uint32_t)rloc * 128 + (uint32_t)((ch8 ^ (rloc & 7)) * 16);
        uint4 val = *(uint4*)(wst + off);
        *(uint4*)(Cout + (size_t)(rowg0 + rloc) * ldC + colg0 + ch8 * 8) = val;
    }
}

// ======================= conversion kernels =================================
__global__ void conv_half2_kernel(const float* __restrict__ x0, __half* __restrict__ d0,
                                  const float* __restrict__ x1, __half* __restrict__ d1) {
    size_t gi = (size_t)blockIdx.x * blockDim.x + threadIdx.x;
    const float* x; __half* d;
    size_t n4 = (size_t)NROWS * NC / 4;
    if (gi < n4) { x = x0; d = d0; }
    else { x = x1; d = d1; gi -= n4; }
    size_t i = gi * 4;
    float4 v = *(const float4*)(x + i);
    __half2 a = __floats2half2_rn(v.x, v.y);
    __half2 b = __floats2half2_rn(v.z, v.w);
    *(uint2*)(d + i) = make_uint2(*(uint32_t*)&a, *(uint32_t*)&b);
}

__global__ void convT_all_kernel(const float* wq, const float* wk, const float* wv,
                                 const float* f1, const float* f2,
                                 __half* tq, __half* tk, __half* tv,
                                 __half* t1, __half* t2) {
    __shared__ float t[32][33];
    int b = blockIdx.x;
    const float* W; __half* T; int K, N;
    if      (b < 64)  { W = wq; T = tq; K = NC;    N = NC;    }
    else if (b < 128) { W = wk; T = tk; K = NC;    N = NC;    b -= 64;  }
    else if (b < 192) { W = wv; T = tv; K = NC;    N = NC;    b -= 128; }
    else if (b < 448) { W = f1; T = t1; K = NC;    N = FFDIM; b -= 192; }
    else              { W = f2; T = t2; K = FFDIM; N = NC;    b -= 448; }
    const int nx = N / 32;
    const int n0 = (b % nx) * 32, k0 = (b / nx) * 32;
    const int tx = threadIdx.x, ty = threadIdx.y;
    for (int i = ty; i < 32; i += 8) t[i][tx] = W[(size_t)(k0 + i) * N + n0 + tx];
    __syncthreads();
    for (int i = ty; i < 32; i += 8)
        T[(size_t)(n0 + i) * K + k0 + tx] = __float2half_rn(t[tx][i]);
}

// ======================= attention middle ===================================
__global__ void colmax_part_kernel() {
    const int chunk = blockIdx.x;
    const int b = chunk / (NSEQ / 256);
    const int r0 = (chunk % (NSEQ / 256)) * 256;
    const int c = threadIdx.x;
    const __half* base = g_Kp + ((size_t)b * NSEQ + r0) * NC;
    float m = -INFINITY;
    for (int r = 0; r < 256; r++)
        m = fmaxf(m, __half2float(base[(size_t)r * NC + c]));
    g_partmax[(size_t)chunk * NC + c] = m;
}
__global__ void colmax_red_kernel() {
    const int b = blockIdx.x;
    const int c = threadIdx.x;
    float m = -INFINITY;
    for (int ch = 0; ch < NSEQ / 256; ch++)
        m = fmaxf(m, g_partmax[((size_t)(b * (NSEQ / 256) + ch)) * NC + c]);
    g_colmax[b * NC + c] = m;
}

// 32-row groups: barriers /4 vs previous 8-row version
#define CGRP 32
__global__ __launch_bounds__(256)
void ctx_part_kernel() {
    const int s  = blockIdx.x;
    const int bh = blockIdx.y;
    const int b = bh / NHEADS;
    const int h = bh % NHEADS;
    const int t = threadIdx.x;
    const int chunk = NSEQ / NSPLIT;     // 1024
    __shared__ float ek[CGRP][DH];
    __shared__ float vv[CGRP][DH];
    const int e  = t & 31;
    const int d0 = (t >> 5) * 4;
    float acc0 = 0.f, acc1 = 0.f, acc2 = 0.f, acc3 = 0.f, zacc = 0.f;
    for (int g = 0; g < chunk / CGRP; g++) {
        #pragma unroll
        for (int i = 0; i < CGRP * 2 * DH / 256; i++) {   // 8
            int idx = t + i * 256;
            int row = idx >> 6;
            int col = idx & 63;
            int n = s * chunk + g * CGRP + row;
            size_t base = ((size_t)b * NSEQ + n) * NC + h * DH;
            if (col < DH) {
                float kv = __half2float(g_Kp[base + col]);
                ek[row][col] = expf(kv - g_colmax[b * NC + h * DH + col]);
            } else {
                vv[row][col - DH] = __half2float(g_Vp[base + (col - DH)]);
            }
        }
        __syncthreads();
        #pragma unroll 8
        for (int row = 0; row < CGRP; row++) {
            float v = vv[row][e];
            acc0 = fmaf(ek[row][d0 + 0], v, acc0);
            acc1 = fmaf(ek[row][d0 + 1], v, acc1);
            acc2 = fmaf(ek[row][d0 + 2], v, acc2);
            acc3 = fmaf(ek[row][d0 + 3], v, acc3);
        }
        if (t < DH) {
            #pragma unroll 8
            for (int row = 0; row < CGRP; row++) zacc += ek[row][t];
        }
        __syncthreads();
    }
    const size_t sp = ((size_t)bh * NSPLIT + s) * (DH * DH);
    g_Spart[sp + (d0 + 0) * DH + e] = acc0;
    g_Spart[sp + (d0 + 1) * DH + e] = acc1;
    g_Spart[sp + (d0 + 2) * DH + e] = acc2;
    g_Spart[sp + (d0 + 3) * DH + e] = acc3;
    if (t < DH) g_Zpart[((size_t)bh * NSPLIT + s) * DH + t] = zacc;
}
__global__ void ctx_reduce_kernel() {
    const int bh = blockIdx.x;
    const int t = threadIdx.x;
    const int d = t >> 5;
    __shared__ float zs[DH];
    float ssum = 0.f;
    for (int p = 0; p < NSPLIT; p++)
        ssum += g_Spart[((size_t)bh * NSPLIT + p) * (DH * DH) + t];
    if (t < DH) {
        float z = 0.f;
        for (int p = 0; p < NSPLIT; p++)
            z += g_Zpart[((size_t)bh * NSPLIT + p) * DH + t];
        zs[t] = z;
    }
    __syncthreads();
    g_ctx[(size_t)bh * (DH * DH) + t] = ssum / zs[d];
}

// fused softmax(Q) -> attn -> +residual -> LN1; two-phase, 1 barrier/block
#define ROWS_PER_BLK 16
__global__ __launch_bounds__(256)
void attn_ln1_kernel(const float* __restrict__ gamma,
                     const float* __restrict__ beta) {
    __shared__ float ys[ROWS_PER_BLK][NC];   // 16KB
    __shared__ float gb[2][NC];              // 2KB
    const int t = threadIdx.x;
    const int h = t >> 5;
    const int lane = t & 31;
    const int row0 = blockIdx.x * ROWS_PER_BLK;
    const int b = row0 / NSEQ;

    // ctx for this thread's head/column in registers (coalesced loads)
    float ctx[DH];
    const float* cb = g_ctx + ((size_t)b * NHEADS + h) * DH * DH;
    #pragma unroll
    for (int d = 0; d < DH; d++) ctx[d] = cb[d * DH + lane];
    gb[0][t] = gamma[t];
    gb[1][t] = beta[t];

    // phase 1: softmax(Q) + attn + residual -> ys (no barriers)
    for (int r = 0; r < ROWS_PER_BLK; r++) {
        const size_t off = (size_t)(row0 + r) * NC;
        float qv = __half2float(g_Qp[off + t]);
        float m = qv;
        #pragma unroll
        for (int s = 16; s > 0; s >>= 1) m = fmaxf(m, __shfl_xor_sync(0xffffffffu, m, s));
        float ev = expf(qv - m);
        float ss = ev;
        #pragma unroll
        for (int s = 16; s > 0; s >>= 1) ss += __shfl_xor_sync(0xffffffffu, ss, s);
        float qn = ev / ss;
        float acc = 0.f;
        #pragma unroll
        for (int d = 0; d < DH; d++) {
            float qd = __shfl_sync(0xffffffffu, qn, d);
            acc = fmaf(qd, ctx[d], acc);
        }
        ys[r][t] = __half2float(g_qh[off + t]) + acc;
    }
    __syncthreads();

    // phase 2: LN warp-per-row (2 rows per warp), no barriers
    #pragma unroll
    for (int rr = 0; rr < ROWS_PER_BLK / 8; rr++) {
        const int r = h * (ROWS_PER_BLK / 8) + rr;
        float v[8], s1 = 0.f, s2 = 0.f;
        #pragma unroll
        for (int j = 0; j < 8; j++) {
            v[j] = ys[r][lane + 32 * j];
            s1 += v[j];
            s2 += v[j] * v[j];
        }
        #pragma unroll
        for (int s = 16; s > 0; s >>= 1) {
            s1 += __shfl_xor_sync(0xffffffffu, s1, s);
            s2 += __shfl_xor_sync(0xffffffffu, s2, s);
        }
        const float mean = s1 * (1.0f / NC);
        const float var  = s2 * (1.0f / NC) - mean * mean;
        const float rs   = rsqrtf(var + LN_EPS);
        const size_t off = (size_t)(row0 + r) * NC;
        #pragma unroll
        for (int j = 0; j < 8; j++) {
            const int c = lane + 32 * j;
            float xv = (v[j] - mean) * rs * gb[0][c] + gb[1][c];
            g_xh[off + c] = __float2half_rn(xv);
        }
    }
}

// ln2 warp-per-row: 8 rows/block, warp-local reductions, no block barriers
__global__ __launch_bounds__(256)
void ln2_kernel(const float* __restrict__ gamma, const float* __restrict__ beta,
                float* __restrict__ out) {
    const int t = threadIdx.x;
    const int h = t >> 5;
    const int lane = t & 31;
    const size_t row = (size_t)blockIdx.x * 8 + h;
    const size_t off = row * NC;
    float v[8], s1 = 0.f, s2 = 0.f;
    #pragma unroll
    for (int j = 0; j < 8; j++) {
        const int c = lane + 32 * j;
        v[j] = __half2float(g_xh[off + c]) + __half2float(g_ffout[off + c]);
        s1 += v[j];
        s2 += v[j] * v[j];
    }
    #pragma unroll
    for (int s = 16; s > 0; s >>= 1) {
        s1 += __shfl_xor_sync(0xffffffffu, s1, s);
        s2 += __shfl_xor_sync(0xffffffffu, s2, s);
    }
    const float mean = s1 * (1.0f / NC);
    const float var  = s2 * (1.0f / NC) - mean * mean;
    const float rs   = rsqrtf(var + LN_EPS);
    #pragma unroll
    for (int j = 0; j < 8; j++) {
        const int c = lane + 32 * j;
        out[off + c] = (v[j] - mean) * rs * gamma[c] + beta[c];
    }
}

// ======================= launch =============================================
extern "C" void kernel_launch(void* const* d_in, const int* in_sizes, int n_in,
                              void* d_out, int out_size) {
    const float* q     = (const float*)d_in[0];
    const float* kv    = (const float*)d_in[1];
    const float* wq_w  = (const float*)d_in[2];
    const float* wq_b  = (const float*)d_in[3];
    const float* wk_w  = (const float*)d_in[4];
    const float* wk_b  = (const float*)d_in[5];
    const float* wv_w  = (const float*)d_in[6];
    const float* wv_b  = (const float*)d_in[7];
    const float* ln1_g = (const float*)d_in[8];
    const float* ln1_b = (const float*)d_in[9];
    const float* ff1_w = (const float*)d_in[10];
    const float* ff1_b = (const float*)d_in[11];
    const float* ff2_w = (const float*)d_in[12];
    const float* ff2_b = (const float*)d_in[13];
    const float* ln2_g = (const float*)d_in[14];
    const float* ln2_b = (const float*)d_in[15];
    float* out = (float*)d_out;

    void *pQ, *pK, *pV, *pF;
    void *pqh, *pkvh, *pxh, *phh;
    void *wq, *wkv, *f1, *f2;
    cudaGetSymbolAddress(&pQ, g_Qp);    cudaGetSymbolAddress(&pK, g_Kp);
    cudaGetSymbolAddress(&pV, g_Vp);    cudaGetSymbolAddress(&pF, g_ffout);
    cudaGetSymbolAddress(&pqh, g_qh);   cudaGetSymbolAddress(&pkvh, g_kvh);
    cudaGetSymbolAddress(&pxh, g_xh);   cudaGetSymbolAddress(&phh, g_hh);
    cudaGetSymbolAddress(&wq, g_wqT);   cudaGetSymbolAddress(&wkv, g_wkvT);
    cudaGetSymbolAddress(&f1, g_f1T);   cudaGetSymbolAddress(&f2, g_f2T);

    cudaFuncSetAttribute(tc_gemm<0,0>, cudaFuncAttributeMaxDynamicSharedMemorySize, GEMM_SMEM);
    cudaFuncSetAttribute(tc_gemm<0,1>, cudaFuncAttributeMaxDynamicSharedMemorySize, GEMM_SMEM);
    cudaFuncSetAttribute(tc_gemm<1,0>, cudaFuncAttributeMaxDynamicSharedMemorySize, GEMM_SMEM);

    const size_t n4 = (size_t)NROWS * NC / 4;
    conv_half2_kernel<<<(int)(2 * n4 / 256), 256>>>(q, (__half*)pqh, kv, (__half*)pkvh);
    dim3 tb(32, 8);
    convT_all_kernel<<<704, tb>>>(wq_w, wk_w, wv_w, ff1_w, ff2_w,
                                  (__half*)wq, (__half*)wkv,
                                  (__half*)wkv + 256 * NC,
                                  (__half*)f1, (__half*)f2);

    // projections: Q alone; K+V fused (shared A)
    dim3 gQ(NC / 128, NROWS / 128);
    tc_gemm<0,0><<<gQ, 128, GEMM_SMEM>>>((__half*)pqh, (__half*)wq, wq_b, 0,
                                         (__half*)pQ, 0, NC, NC);
    dim3 gKV(512 / 128, NROWS / 128);
    tc_gemm<0,1><<<gKV, 128, GEMM_SMEM>>>((__half*)pkvh, (__half*)wkv, wk_b, wv_b,
                                          (__half*)pK, (__half*)pV, 512, NC);

    // attention middle
    colmax_part_kernel<<<BATCH * (NSEQ / 256), 256>>>();
    colmax_red_kernel<<<BATCH, 256>>>();
    ctx_part_kernel<<<dim3(NSPLIT, BATCH * NHEADS), 256>>>();
    ctx_reduce_kernel<<<BATCH * NHEADS, DH * DH>>>();
    attn_ln1_kernel<<<NROWS / ROWS_PER_BLK, 256>>>(ln1_g, ln1_b);

    // FF
    dim3 gFF1(FFDIM / 128, NROWS / 128);
    tc_gemm<1,0><<<gFF1, 128, GEMM_SMEM>>>((__half*)pxh, (__half*)f1, ff1_b, 0,
                                           (__half*)phh, 0, FFDIM, NC);
    dim3 gFF2(NC / 128, NROWS / 128);
    tc_gemm<0,0><<<gFF2, 128, GEMM_SMEM>>>((__half*)phh, (__half*)f2, ff2_b, 0,
                                           (__half*)pF, 0, NC, FFDIM);

    ln2_kernel<<<NROWS / 8, 256>>>(ln2_g, ln2_b, out);
}